// round 8
// baseline (speedup 1.0000x reference)
#include <cuda_runtime.h>

#define PI_D 3.14159265358979323846
#define NN   512
#define N2   262144
#define NIMG 144
#define GSIZE 8           // images per pipeline group (L2-resident window)
#define NG    18          // number of groups
#define BPS   (GSIZE*64)  // blocks per pass-slice = 512
#define RSTRIDE 584       // row kernels: warp stays within one region
#define CSTRIDE 578       // col kernels: conflict-free across regions
#define SK(i) ((i) + ((i)>>3))

// ---------------- device scratch (no allocations allowed) ----------------
static __device__ float2 d_field[(size_t)NIMG*N2];   // ~302 MB, in-place field
static __device__ float2 d_Tl[3*N2];                 // layer transmissions
static __device__ float2 d_Hb[N2];                   // H / N^2
static __device__ float2 d_Hb2[N2];                  // H^2 / N^2
static __device__ float2 d_tw[NN];                   // e^{-2pi i k/512}
static __device__ unsigned char d_cls[N2];           // pixel -> class (255 = none)
static __device__ float d_part[NIMG*64*10];          // per-block class partials

__device__ __forceinline__ float2 cmul(float2 a, float2 b){
    return make_float2(a.x*b.x - a.y*b.y, a.x*b.y + a.y*b.x);
}

#define BREV_DECL const int brev[8] = {0,4,2,6,1,5,3,7}

// ---------------- radix-8 butterfly (DIF, output bit-reversed) ----------------
template<bool INV>
__device__ __forceinline__ void fft8(float2 v[8]){
    const float C0 = 0.70710678118654752440f;
    float2 t;
#define BTF(a,b) { t = a; a.x = t.x + b.x; a.y = t.y + b.y; b.x = t.x - b.x; b.y = t.y - b.y; }
    BTF(v[0],v[4]); BTF(v[1],v[5]); BTF(v[2],v[6]); BTF(v[3],v[7]);
    if (INV){
        v[5] = cmul(v[5], make_float2(C0,  C0));
        v[6] = make_float2(-v[6].y,  v[6].x);
        v[7] = cmul(v[7], make_float2(-C0, C0));
    } else {
        v[5] = cmul(v[5], make_float2(C0, -C0));
        v[6] = make_float2( v[6].y, -v[6].x);
        v[7] = cmul(v[7], make_float2(-C0,-C0));
    }
    BTF(v[0],v[2]); BTF(v[1],v[3]); BTF(v[4],v[6]); BTF(v[5],v[7]);
    if (INV){ v[3] = make_float2(-v[3].y, v[3].x); v[7] = make_float2(-v[7].y, v[7].x); }
    else    { v[3] = make_float2( v[3].y,-v[3].x); v[7] = make_float2( v[7].y,-v[7].x); }
    BTF(v[0],v[1]); BTF(v[2],v[3]); BTF(v[4],v[5]); BTF(v[6],v[7]);
#undef BTF
}

// apply brev permutation in registers (pure renaming, elided by ptxas)
__device__ __forceinline__ void permute_brev(float2 v[8]){
    BREV_DECL;
    float2 t[8];
#pragma unroll
    for (int r=0;r<8;r++) t[r] = v[brev[r]];
#pragma unroll
    for (int r=0;r<8;r++) v[r] = t[r];
}

// ---- dual-slot 512-pt FFT, ONE line, thread owns slots j and j+32 (j in 0..31)
template<bool INV, bool PERM>
__device__ __forceinline__ void fft512_dual(float2 v[8], float2 w[8],
                                            float2* s, int j, const float2* tw){
    BREV_DECL;
    if (PERM){ permute_brev(v); permute_brev(w); }
    fft8<INV>(v); fft8<INV>(w);
#pragma unroll
    for (int r=0;r<8;r++){ s[SK(8*j+r)] = v[brev[r]]; s[SK(8*(j+32)+r)] = w[brev[r]]; }
    __syncthreads();
#pragma unroll
    for (int r=0;r<8;r++){ v[r] = s[SK(j+64*r)]; w[r] = s[SK(j+32+64*r)]; }
    int jm = j & 7;
#pragma unroll
    for (int r=1;r<8;r++){
        float2 q = tw[r*jm*8];
        if (INV) q.y = -q.y;
        v[r] = cmul(v[r], q); w[r] = cmul(w[r], q);   // (j+32)&7 == j&7
    }
    fft8<INV>(v); fft8<INV>(w);
    int iv = ((j - jm) << 3) + jm;
    int iw = iv + 256;
    __syncthreads();
#pragma unroll
    for (int r=0;r<8;r++){ s[SK(iv + 8*r)] = v[brev[r]]; s[SK(iw + 8*r)] = w[brev[r]]; }
    __syncthreads();
#pragma unroll
    for (int r=0;r<8;r++){ v[r] = s[SK(j+64*r)]; w[r] = s[SK(j+32+64*r)]; }
#pragma unroll
    for (int r=1;r<8;r++){
        float2 qv = tw[r*j], qw = tw[r*(j+32)];
        if (INV){ qv.y = -qv.y; qw.y = -qw.y; }
        v[r] = cmul(v[r], qv); w[r] = cmul(w[r], qw);
    }
    fft8<INV>(v); fft8<INV>(w);
}

// ---- dual-line 512-pt FFT: TWO independent lines (regions sA, sB), slot j (0..63)
template<bool INV, bool PERM>
__device__ __forceinline__ void fft512_dual2(float2 v[8], float2 w[8],
                                             float2* sA, float2* sB, int j,
                                             const float2* tw){
    BREV_DECL;
    if (PERM){ permute_brev(v); permute_brev(w); }
    fft8<INV>(v); fft8<INV>(w);
#pragma unroll
    for (int r=0;r<8;r++){ sA[SK(8*j+r)] = v[brev[r]]; sB[SK(8*j+r)] = w[brev[r]]; }
    __syncthreads();
#pragma unroll
    for (int r=0;r<8;r++){ v[r] = sA[SK(j+64*r)]; w[r] = sB[SK(j+64*r)]; }
    int jm = j & 7;
#pragma unroll
    for (int r=1;r<8;r++){
        float2 q = tw[r*jm*8];
        if (INV) q.y = -q.y;
        v[r] = cmul(v[r], q); w[r] = cmul(w[r], q);
    }
    fft8<INV>(v); fft8<INV>(w);
    int idxD = ((j - jm) << 3) + jm;
    __syncthreads();
#pragma unroll
    for (int r=0;r<8;r++){ sA[SK(idxD + 8*r)] = v[brev[r]]; sB[SK(idxD + 8*r)] = w[brev[r]]; }
    __syncthreads();
#pragma unroll
    for (int r=0;r<8;r++){ v[r] = sA[SK(j+64*r)]; w[r] = sB[SK(j+64*r)]; }
#pragma unroll
    for (int r=1;r<8;r++){
        float2 q = tw[r*j];
        if (INV) q.y = -q.y;
        v[r] = cmul(v[r], q); w[r] = cmul(w[r], q);
    }
    fft8<INV>(v); fft8<INV>(w);
}

// ---------------- init kernels ----------------
__global__ void k_tw(){
    int t = threadIdx.x;
    double ang = -2.0*PI_D*(double)t/512.0;
    d_tw[t] = make_float2((float)cos(ang), (float)sin(ang));
}

__global__ void k_init(const float* __restrict__ amp, const float* __restrict__ phs,
                       const float* __restrict__ mask){
    int i = blockIdx.x, j = threadIdx.x;
    int idx = i*NN + j;
    float inv = 1.0f/(512.0f*8e-6f);
    float fx = (float)(i<256 ? i : i-512) * inv;
    float fy = (float)(j<256 ? j : j-512) * inv;
    const float lam = 5.32e-7f;
    float lx = lam*fx, ly = lam*fy;
    float arg = 1.0f - lx*lx - ly*ly;
    float sa = sqrtf(fmaxf(arg, 0.0f));
    const float KZ = (float)(2.0*PI_D/5.32e-7*0.05);
    float phi = KZ * sa;                   // f32 rounding, matches jax path
    double s, c;
    sincos((double)phi, &s, &c);           // accurate for huge args
    float hr = (float)c, hi = (float)s;
    const float sc = 1.0f/262144.0f;
    d_Hb [idx] = make_float2(hr*sc, hi*sc);
    d_Hb2[idx] = make_float2((hr*hr - hi*hi)*sc, 2.0f*hr*hi*sc);
#pragma unroll
    for (int l=0;l<3;l++){
        float a = amp[l*N2+idx], p = phs[l*N2+idx];
        float sn, cs; sincosf(p, &sn, &cs);
        d_Tl[l*N2+idx] = make_float2(a*cs, a*sn);
    }
    unsigned char cl = 255;
#pragma unroll
    for (int q=0;q<10;q++) if (mask[q*N2 + idx] > 0.5f) cl = (unsigned char)q;
    d_cls[idx] = cl;
}

// ---------------- pass bodies (device functions) ----------------

__device__ __forceinline__ void body_p1(float2* S, float2* TW,
                                        const float* __restrict__ xamp,
                                        const float* __restrict__ pn,
                                        int inner, int img0){
    int t = threadIdx.x;
    int line = t >> 5, j = t & 31;
    int img  = img0 + (inner >> 6);
    int row  = ((inner & 63) << 3) + line;
    int b = img & 15, m = img >> 4;
    float fm = 0.5f * (float)(m+1);
    size_t ibase = (size_t)img*N2 + (size_t)row*NN;
    size_t bbase = (size_t)b  *N2 + (size_t)row*NN;
    float2 v[8], w[8];
#pragma unroll
    for (int r=0;r<8;r++){
        int e1 = j + 64*r, e2 = j + 32 + 64*r;
        float p1v = pn[ibase + e1], p2v = pn[ibase + e2];
        float x1 = xamp[bbase + e1], x2 = xamp[bbase + e2];
        float sn, cs;
        __sincosf(p1v*fm, &sn, &cs);
        float2 a = make_float2(x1*cs, x1*sn);
        v[r] = cmul(a, d_Tl[row*NN + e1]);
        __sincosf(p2v*fm, &sn, &cs);
        float2 bb = make_float2(x2*cs, x2*sn);
        w[r] = cmul(bb, d_Tl[row*NN + e2]);
    }
    fft512_dual<false,false>(v, w, S + line*RSTRIDE, j, TW);
    BREV_DECL;
#pragma unroll
    for (int r=0;r<8;r++){
        d_field[ibase + j + 64*r]      = v[brev[r]];
        d_field[ibase + j + 32 + 64*r] = w[brev[r]];
    }
}

__device__ __forceinline__ void body_col(float2* S, float2* TW,
                                         const float2* __restrict__ Hm,
                                         int inner, int img0){
    int t = threadIdx.x;
    int p = t & 3, j = t >> 2;          // pair id, slot
    int img = img0 + (inner >> 6);
    int colA = ((inner & 63) << 3) + 2*p;
    size_t ibase = (size_t)img*N2;
    BREV_DECL;
    float2 v[8], w[8];
#pragma unroll
    for (int r=0;r<8;r++){
        float4 F = *(const float4*)&d_field[ibase + (size_t)(j+64*r)*NN + colA];
        v[r] = make_float2(F.x, F.y);
        w[r] = make_float2(F.z, F.w);
    }
    float2* sA = S + (2*p  )*CSTRIDE;
    float2* sB = S + (2*p+1)*CSTRIDE;
    fft512_dual2<false,false>(v, w, sA, sB, j, TW);
    // in-place spectral multiply: v[i] holds elem j+64*brev[i]
#pragma unroll
    for (int i=0;i<8;i++){
        float4 Hp = *(const float4*)&Hm[(j+64*brev[i])*NN + colA];
        v[i] = cmul(v[i], make_float2(Hp.x, Hp.y));
        w[i] = cmul(w[i], make_float2(Hp.z, Hp.w));
    }
    __syncthreads();    // S free for second FFT
    fft512_dual2<true,true>(v, w, sA, sB, j, TW);
#pragma unroll
    for (int r=0;r<8;r++){
        float4 F;
        F.x = v[brev[r]].x; F.y = v[brev[r]].y;
        F.z = w[brev[r]].x; F.w = w[brev[r]].y;
        *(float4*)&d_field[ibase + (size_t)(j+64*r)*NN + colA] = F;
    }
}

__device__ __forceinline__ void body_mid(float2* S, float2* TW, int l,
                                         int inner, int img0){
    int t = threadIdx.x;
    int line = t >> 5, j = t & 31;
    int img  = img0 + (inner >> 6);
    int row  = ((inner & 63) << 3) + line;
    size_t ibase = (size_t)img*N2 + (size_t)row*NN;
    BREV_DECL;
    float2 v[8], w[8];
#pragma unroll
    for (int r=0;r<8;r++){
        v[r] = d_field[ibase + j + 64*r];
        w[r] = d_field[ibase + j + 32 + 64*r];
    }
    float2* s = S + line*RSTRIDE;
    fft512_dual<true,false>(v, w, s, j, TW);
    const float2* __restrict__ T = d_Tl + l*N2 + row*NN;
#pragma unroll
    for (int i=0;i<8;i++){
        v[i] = cmul(v[i], T[j + 64*brev[i]]);
        w[i] = cmul(w[i], T[j + 32 + 64*brev[i]]);
    }
    __syncthreads();
    fft512_dual<false,true>(v, w, s, j, TW);
#pragma unroll
    for (int r=0;r<8;r++){
        d_field[ibase + j + 64*r]      = v[brev[r]];
        d_field[ibase + j + 32 + 64*r] = w[brev[r]];
    }
}

__device__ __forceinline__ void body_p7(float2* S, float2* TW, float (*WP)[10],
                                        int inner, int img0){
    int t = threadIdx.x;
    int line = t >> 5, j = t & 31;
    int img  = img0 + (inner >> 6);
    int chunk = inner & 63;
    int row  = (chunk << 3) + line;
    size_t ibase = (size_t)img*N2 + (size_t)row*NN;
    BREV_DECL;
    float2 v[8], w[8];
#pragma unroll
    for (int r=0;r<8;r++){
        v[r] = d_field[ibase + j + 64*r];
        w[r] = d_field[ibase + j + 32 + 64*r];
    }
    fft512_dual<true,false>(v, w, S + line*RSTRIDE, j, TW);

    float acc[10];
#pragma unroll
    for (int q=0;q<10;q++) acc[q] = 0.f;
#pragma unroll
    for (int i=0;i<8;i++){
        float2 f = v[i];
        float I = f.x*f.x + f.y*f.y;
        int cl = d_cls[row*NN + j + 64*brev[i]];
#pragma unroll
        for (int q=0;q<10;q++) if (cl==q) acc[q] += I;
        f = w[i];
        I = f.x*f.x + f.y*f.y;
        cl = d_cls[row*NN + j + 32 + 64*brev[i]];
#pragma unroll
        for (int q=0;q<10;q++) if (cl==q) acc[q] += I;
    }
#pragma unroll
    for (int q=0;q<10;q++){
#pragma unroll
        for (int o=16;o>0;o>>=1)
            acc[q] += __shfl_xor_sync(0xffffffffu, acc[q], o);
    }
    if (j == 0){
#pragma unroll
        for (int q=0;q<10;q++) WP[line][q] = acc[q];
    }
    __syncthreads();
    if (t < 10){
        float s = 0.f;
#pragma unroll
        for (int q=0;q<8;q++) s += WP[q][t];
        d_part[(img*64 + chunk)*10 + t] = s;
    }
}

// ---------------- mega kernel: software-pipelined pass dispatch ----------------
// Launch i contains pass p = i - g for every group g with 0 <= i-g <= 6.
// Slices within a launch touch disjoint image ranges -> independent.
__global__ void __launch_bounds__(256,4) mega(int i, int gmin,
                                              const float* __restrict__ xamp,
                                              const float* __restrict__ pn){
    __shared__ float2 S[8*RSTRIDE];   // RSTRIDE >= CSTRIDE
    __shared__ float2 TW[NN];
    __shared__ float WP[8][10];
    int t = threadIdx.x;
    TW[t] = d_tw[t]; TW[t+256] = d_tw[t+256];

    int slice = blockIdx.x / BPS;
    int inner = blockIdx.x - slice * BPS;
    int g = gmin + slice;
    int p = i - g;
    int img0 = g * GSIZE;

    switch (p){
        case 0: body_p1 (S, TW, xamp, pn, inner, img0); break;
        case 1: body_col(S, TW, d_Hb,  inner, img0); break;
        case 2: body_mid(S, TW, 1,     inner, img0); break;
        case 3: body_col(S, TW, d_Hb,  inner, img0); break;
        case 4: body_mid(S, TW, 2,     inner, img0); break;
        case 5: body_col(S, TW, d_Hb2, inner, img0); break;   // fused last two props
        default: body_p7(S, TW, WP,    inner, img0); break;
    }
}

// final: sum over 9 modes x 64 chunks, /9, scores [16,10]
__global__ void redB(float* __restrict__ out){
    __shared__ float sh[64];
    int t = threadIdx.x;
    int b = blockIdx.x / 10, c = blockIdx.x % 10;
    float s = 0.f;
#pragma unroll
    for (int m=0;m<9;m++)
        s += d_part[(((m*16+b) << 6) + t)*10 + c];
    sh[t] = s; __syncthreads();
    for (int w=32; w>0; w>>=1){ if (t < w) sh[t] += sh[t+w]; __syncthreads(); }
    if (t==0) out[blockIdx.x] = sh[0] * (1.0f/9.0f);
}

// ---------------- launch ----------------
extern "C" void kernel_launch(void* const* d_in, const int* in_sizes, int n_in,
                              void* d_out, int out_size){
    const float* x_amp  = (const float*)d_in[0];
    const float* pnoise = (const float*)d_in[1];
    const float* amp    = (const float*)d_in[2];
    const float* phs    = (const float*)d_in[3];
    const float* mask   = (const float*)d_in[4];
    float* out = (float*)d_out;

    k_tw  <<<1,   512>>>();
    k_init<<<512, 512>>>(amp, phs, mask);

    // pipelined schedule: launch i runs pass (i-g) of group g for all valid g;
    // GSIZE=8 keeps the whole in-flight window (~120MB) L2-resident.
    for (int i = 0; i < NG + 6; i++){
        int gmin = (i > 6) ? (i - 6) : 0;
        int gmax = (i < NG-1) ? i : (NG-1);
        int ns = gmax - gmin + 1;
        mega<<<ns*BPS, 256>>>(i, gmin, x_amp, pnoise);
    }
    redB<<<160, 64>>>(out);
}

// round 9
// speedup vs baseline: 1.0936x; 1.0936x over previous
#include <cuda_runtime.h>

#define PI_D 3.14159265358979323846
#define NN   512
#define N2   262144
#define NIMG 144
#define GSIZE 24          // images per pipeline group
#define NG    6           // number of groups
#define BPS   (GSIZE*64)  // blocks per pass-slice = 1536
#define RSTRIDE 584       // row kernels: warp stays within one region
#define CSTRIDE 578       // col kernels: conflict-free across regions
#define TWSZ   584        // skewed twiddle table (max SK(511)=574)
#define SK(i) ((i) + ((i)>>3))

// ---------------- device scratch (no allocations allowed) ----------------
static __device__ float2 d_field[(size_t)NIMG*N2];   // ~302 MB, in-place field
static __device__ float2 d_Tl[3*N2];                 // layer transmissions
static __device__ float2 d_Hb[N2];                   // H / N^2
static __device__ float2 d_Hb2[N2];                  // H^2 / N^2
static __device__ float2 d_tw[NN];                   // e^{-2pi i k/512}
static __device__ unsigned char d_cls[N2];           // pixel -> class (255 = none)
static __device__ float d_part[NIMG*64*10];          // per-block class partials

__device__ __forceinline__ float2 cmul(float2 a, float2 b){
    return make_float2(a.x*b.x - a.y*b.y, a.x*b.y + a.y*b.x);
}

#define BREV_DECL const int brev[8] = {0,4,2,6,1,5,3,7}

// ---------------- radix-8 butterfly (DIF, output bit-reversed) ----------------
template<bool INV>
__device__ __forceinline__ void fft8(float2 v[8]){
    const float C0 = 0.70710678118654752440f;
    float2 t;
#define BTF(a,b) { t = a; a.x = t.x + b.x; a.y = t.y + b.y; b.x = t.x - b.x; b.y = t.y - b.y; }
    BTF(v[0],v[4]); BTF(v[1],v[5]); BTF(v[2],v[6]); BTF(v[3],v[7]);
    if (INV){
        v[5] = cmul(v[5], make_float2(C0,  C0));
        v[6] = make_float2(-v[6].y,  v[6].x);
        v[7] = cmul(v[7], make_float2(-C0, C0));
    } else {
        v[5] = cmul(v[5], make_float2(C0, -C0));
        v[6] = make_float2( v[6].y, -v[6].x);
        v[7] = cmul(v[7], make_float2(-C0,-C0));
    }
    BTF(v[0],v[2]); BTF(v[1],v[3]); BTF(v[4],v[6]); BTF(v[5],v[7]);
    if (INV){ v[3] = make_float2(-v[3].y, v[3].x); v[7] = make_float2(-v[7].y, v[7].x); }
    else    { v[3] = make_float2( v[3].y,-v[3].x); v[7] = make_float2( v[7].y,-v[7].x); }
    BTF(v[0],v[1]); BTF(v[2],v[3]); BTF(v[4],v[5]); BTF(v[6],v[7]);
#undef BTF
}

// apply brev permutation in registers (pure renaming, elided by ptxas)
__device__ __forceinline__ void permute_brev(float2 v[8]){
    BREV_DECL;
    float2 t[8];
#pragma unroll
    for (int r=0;r<8;r++) t[r] = v[brev[r]];
#pragma unroll
    for (int r=0;r<8;r++) v[r] = t[r];
}

// NOTE: twiddle table tw[] is stored SKEWED: logical tw[k] lives at tw[SK(k)].
// This kills the severe (up to 8-way) bank conflicts of the raw k=8*r*jm / r*j
// access patterns.

// ---- dual-slot 512-pt FFT, ONE line, thread owns slots j and j+32 (j in 0..31)
template<bool INV, bool PERM>
__device__ __forceinline__ void fft512_dual(float2 v[8], float2 w[8],
                                            float2* s, int j, const float2* tw){
    BREV_DECL;
    if (PERM){ permute_brev(v); permute_brev(w); }
    fft8<INV>(v); fft8<INV>(w);
#pragma unroll
    for (int r=0;r<8;r++){ s[SK(8*j+r)] = v[brev[r]]; s[SK(8*(j+32)+r)] = w[brev[r]]; }
    __syncthreads();
#pragma unroll
    for (int r=0;r<8;r++){ v[r] = s[SK(j+64*r)]; w[r] = s[SK(j+32+64*r)]; }
    int jm = j & 7;
#pragma unroll
    for (int r=1;r<8;r++){
        float2 q = tw[SK(r*jm*8)];
        if (INV) q.y = -q.y;
        v[r] = cmul(v[r], q); w[r] = cmul(w[r], q);   // (j+32)&7 == j&7
    }
    fft8<INV>(v); fft8<INV>(w);
    int iv = ((j - jm) << 3) + jm;
    int iw = iv + 256;
    __syncthreads();
#pragma unroll
    for (int r=0;r<8;r++){ s[SK(iv + 8*r)] = v[brev[r]]; s[SK(iw + 8*r)] = w[brev[r]]; }
    __syncthreads();
#pragma unroll
    for (int r=0;r<8;r++){ v[r] = s[SK(j+64*r)]; w[r] = s[SK(j+32+64*r)]; }
#pragma unroll
    for (int r=1;r<8;r++){
        float2 qv = tw[SK(r*j)], qw = tw[SK(r*(j+32))];
        if (INV){ qv.y = -qv.y; qw.y = -qw.y; }
        v[r] = cmul(v[r], qv); w[r] = cmul(w[r], qw);
    }
    fft8<INV>(v); fft8<INV>(w);
}

// ---- dual-line 512-pt FFT: TWO independent lines (regions sA, sB), slot j (0..63)
template<bool INV, bool PERM>
__device__ __forceinline__ void fft512_dual2(float2 v[8], float2 w[8],
                                             float2* sA, float2* sB, int j,
                                             const float2* tw){
    BREV_DECL;
    if (PERM){ permute_brev(v); permute_brev(w); }
    fft8<INV>(v); fft8<INV>(w);
#pragma unroll
    for (int r=0;r<8;r++){ sA[SK(8*j+r)] = v[brev[r]]; sB[SK(8*j+r)] = w[brev[r]]; }
    __syncthreads();
#pragma unroll
    for (int r=0;r<8;r++){ v[r] = sA[SK(j+64*r)]; w[r] = sB[SK(j+64*r)]; }
    int jm = j & 7;
#pragma unroll
    for (int r=1;r<8;r++){
        float2 q = tw[SK(r*jm*8)];
        if (INV) q.y = -q.y;
        v[r] = cmul(v[r], q); w[r] = cmul(w[r], q);
    }
    fft8<INV>(v); fft8<INV>(w);
    int idxD = ((j - jm) << 3) + jm;
    __syncthreads();
#pragma unroll
    for (int r=0;r<8;r++){ sA[SK(idxD + 8*r)] = v[brev[r]]; sB[SK(idxD + 8*r)] = w[brev[r]]; }
    __syncthreads();
#pragma unroll
    for (int r=0;r<8;r++){ v[r] = sA[SK(j+64*r)]; w[r] = sB[SK(j+64*r)]; }
#pragma unroll
    for (int r=1;r<8;r++){
        float2 q = tw[SK(r*j)];
        if (INV) q.y = -q.y;
        v[r] = cmul(v[r], q); w[r] = cmul(w[r], q);
    }
    fft8<INV>(v); fft8<INV>(w);
}

// ---------------- init kernels ----------------
__global__ void k_tw(){
    int t = threadIdx.x;
    double ang = -2.0*PI_D*(double)t/512.0;
    d_tw[t] = make_float2((float)cos(ang), (float)sin(ang));
}

__global__ void k_init(const float* __restrict__ amp, const float* __restrict__ phs,
                       const float* __restrict__ mask){
    int i = blockIdx.x, j = threadIdx.x;
    int idx = i*NN + j;
    float inv = 1.0f/(512.0f*8e-6f);
    float fx = (float)(i<256 ? i : i-512) * inv;
    float fy = (float)(j<256 ? j : j-512) * inv;
    const float lam = 5.32e-7f;
    float lx = lam*fx, ly = lam*fy;
    float arg = 1.0f - lx*lx - ly*ly;
    float sa = sqrtf(fmaxf(arg, 0.0f));
    const float KZ = (float)(2.0*PI_D/5.32e-7*0.05);
    float phi = KZ * sa;                   // f32 rounding, matches jax path
    double s, c;
    sincos((double)phi, &s, &c);           // accurate for huge args
    float hr = (float)c, hi = (float)s;
    const float sc = 1.0f/262144.0f;
    d_Hb [idx] = make_float2(hr*sc, hi*sc);
    d_Hb2[idx] = make_float2((hr*hr - hi*hi)*sc, 2.0f*hr*hi*sc);
#pragma unroll
    for (int l=0;l<3;l++){
        float a = amp[l*N2+idx], p = phs[l*N2+idx];
        float sn, cs; sincosf(p, &sn, &cs);
        d_Tl[l*N2+idx] = make_float2(a*cs, a*sn);
    }
    unsigned char cl = 255;
#pragma unroll
    for (int q=0;q<10;q++) if (mask[q*N2 + idx] > 0.5f) cl = (unsigned char)q;
    d_cls[idx] = cl;
}

// ---------------- pass bodies (device functions) ----------------

__device__ __forceinline__ void body_p1(float2* S, float2* TW,
                                        const float* __restrict__ xamp,
                                        const float* __restrict__ pn,
                                        int inner, int img0){
    int t = threadIdx.x;
    int line = t >> 5, j = t & 31;
    int img  = img0 + (inner >> 6);
    int row  = ((inner & 63) << 3) + line;
    int b = img & 15, m = img >> 4;
    float fm = 0.5f * (float)(m+1);
    size_t ibase = (size_t)img*N2 + (size_t)row*NN;
    size_t bbase = (size_t)b  *N2 + (size_t)row*NN;
    float2 v[8], w[8];
#pragma unroll
    for (int r=0;r<8;r++){
        int e1 = j + 64*r, e2 = j + 32 + 64*r;
        float p1v = pn[ibase + e1], p2v = pn[ibase + e2];
        float x1 = xamp[bbase + e1], x2 = xamp[bbase + e2];
        float sn, cs;
        __sincosf(p1v*fm, &sn, &cs);
        float2 a = make_float2(x1*cs, x1*sn);
        v[r] = cmul(a, d_Tl[row*NN + e1]);
        __sincosf(p2v*fm, &sn, &cs);
        float2 bb = make_float2(x2*cs, x2*sn);
        w[r] = cmul(bb, d_Tl[row*NN + e2]);
    }
    fft512_dual<false,false>(v, w, S + line*RSTRIDE, j, TW);
    BREV_DECL;
#pragma unroll
    for (int r=0;r<8;r++){
        d_field[ibase + j + 64*r]      = v[brev[r]];
        d_field[ibase + j + 32 + 64*r] = w[brev[r]];
    }
}

__device__ __forceinline__ void body_col(float2* S, float2* TW,
                                         const float2* __restrict__ Hm,
                                         int inner, int img0){
    int t = threadIdx.x;
    int p = t & 3, j = t >> 2;          // pair id, slot
    int img = img0 + (inner >> 6);
    int colA = ((inner & 63) << 3) + 2*p;
    size_t ibase = (size_t)img*N2;
    BREV_DECL;
    float2 v[8], w[8];
#pragma unroll
    for (int r=0;r<8;r++){
        float4 F = *(const float4*)&d_field[ibase + (size_t)(j+64*r)*NN + colA];
        v[r] = make_float2(F.x, F.y);
        w[r] = make_float2(F.z, F.w);
    }
    float2* sA = S + (2*p  )*CSTRIDE;
    float2* sB = S + (2*p+1)*CSTRIDE;
    fft512_dual2<false,false>(v, w, sA, sB, j, TW);
    // in-place spectral multiply: v[i] holds elem j+64*brev[i]
#pragma unroll
    for (int i=0;i<8;i++){
        float4 Hp = *(const float4*)&Hm[(j+64*brev[i])*NN + colA];
        v[i] = cmul(v[i], make_float2(Hp.x, Hp.y));
        w[i] = cmul(w[i], make_float2(Hp.z, Hp.w));
    }
    __syncthreads();    // S free for second FFT
    fft512_dual2<true,true>(v, w, sA, sB, j, TW);
#pragma unroll
    for (int r=0;r<8;r++){
        float4 F;
        F.x = v[brev[r]].x; F.y = v[brev[r]].y;
        F.z = w[brev[r]].x; F.w = w[brev[r]].y;
        *(float4*)&d_field[ibase + (size_t)(j+64*r)*NN + colA] = F;
    }
}

__device__ __forceinline__ void body_mid(float2* S, float2* TW, int l,
                                         int inner, int img0){
    int t = threadIdx.x;
    int line = t >> 5, j = t & 31;
    int img  = img0 + (inner >> 6);
    int row  = ((inner & 63) << 3) + line;
    size_t ibase = (size_t)img*N2 + (size_t)row*NN;
    BREV_DECL;
    float2 v[8], w[8];
#pragma unroll
    for (int r=0;r<8;r++){
        v[r] = d_field[ibase + j + 64*r];
        w[r] = d_field[ibase + j + 32 + 64*r];
    }
    float2* s = S + line*RSTRIDE;
    fft512_dual<true,false>(v, w, s, j, TW);
    const float2* __restrict__ T = d_Tl + l*N2 + row*NN;
#pragma unroll
    for (int i=0;i<8;i++){
        v[i] = cmul(v[i], T[j + 64*brev[i]]);
        w[i] = cmul(w[i], T[j + 32 + 64*brev[i]]);
    }
    __syncthreads();
    fft512_dual<false,true>(v, w, s, j, TW);
#pragma unroll
    for (int r=0;r<8;r++){
        d_field[ibase + j + 64*r]      = v[brev[r]];
        d_field[ibase + j + 32 + 64*r] = w[brev[r]];
    }
}

__device__ __forceinline__ void body_p7(float2* S, float2* TW, float (*WP)[10],
                                        int inner, int img0){
    int t = threadIdx.x;
    int line = t >> 5, j = t & 31;
    int img  = img0 + (inner >> 6);
    int chunk = inner & 63;
    int row  = (chunk << 3) + line;
    size_t ibase = (size_t)img*N2 + (size_t)row*NN;
    BREV_DECL;
    float2 v[8], w[8];
#pragma unroll
    for (int r=0;r<8;r++){
        v[r] = d_field[ibase + j + 64*r];
        w[r] = d_field[ibase + j + 32 + 64*r];
    }
    fft512_dual<true,false>(v, w, S + line*RSTRIDE, j, TW);

    float acc[10];
#pragma unroll
    for (int q=0;q<10;q++) acc[q] = 0.f;
#pragma unroll
    for (int i=0;i<8;i++){
        float2 f = v[i];
        float I = f.x*f.x + f.y*f.y;
        int cl = d_cls[row*NN + j + 64*brev[i]];
#pragma unroll
        for (int q=0;q<10;q++) if (cl==q) acc[q] += I;
        f = w[i];
        I = f.x*f.x + f.y*f.y;
        cl = d_cls[row*NN + j + 32 + 64*brev[i]];
#pragma unroll
        for (int q=0;q<10;q++) if (cl==q) acc[q] += I;
    }
#pragma unroll
    for (int q=0;q<10;q++){
#pragma unroll
        for (int o=16;o>0;o>>=1)
            acc[q] += __shfl_xor_sync(0xffffffffu, acc[q], o);
    }
    if (j == 0){
#pragma unroll
        for (int q=0;q<10;q++) WP[line][q] = acc[q];
    }
    __syncthreads();
    if (t < 10){
        float s = 0.f;
#pragma unroll
        for (int q=0;q<8;q++) s += WP[q][t];
        d_part[(img*64 + chunk)*10 + t] = s;
    }
}

// ---------------- mega kernel: software-pipelined pass dispatch ----------------
// Launch i contains pass p = i - g for every group g with 0 <= i-g <= 6.
// Slices within a launch touch disjoint image ranges -> independent.
__global__ void __launch_bounds__(256,4) mega(int i, int gmin,
                                              const float* __restrict__ xamp,
                                              const float* __restrict__ pn){
    __shared__ float2 S[8*RSTRIDE];   // RSTRIDE >= CSTRIDE
    __shared__ float2 TW[TWSZ];       // skewed twiddle table
    __shared__ float WP[8][10];
    int t = threadIdx.x;
    TW[SK(t)] = d_tw[t]; TW[SK(t+256)] = d_tw[t+256];

    int slice = blockIdx.x / BPS;
    int inner = blockIdx.x - slice * BPS;
    int g = gmin + slice;
    int p = i - g;
    int img0 = g * GSIZE;

    switch (p){
        case 0: body_p1 (S, TW, xamp, pn, inner, img0); break;
        case 1: body_col(S, TW, d_Hb,  inner, img0); break;
        case 2: body_mid(S, TW, 1,     inner, img0); break;
        case 3: body_col(S, TW, d_Hb,  inner, img0); break;
        case 4: body_mid(S, TW, 2,     inner, img0); break;
        case 5: body_col(S, TW, d_Hb2, inner, img0); break;   // fused last two props
        default: body_p7(S, TW, WP,    inner, img0); break;
    }
}

// final: sum over 9 modes x 64 chunks, /9, scores [16,10]
__global__ void redB(float* __restrict__ out){
    __shared__ float sh[64];
    int t = threadIdx.x;
    int b = blockIdx.x / 10, c = blockIdx.x % 10;
    float s = 0.f;
#pragma unroll
    for (int m=0;m<9;m++)
        s += d_part[(((m*16+b) << 6) + t)*10 + c];
    sh[t] = s; __syncthreads();
    for (int w=32; w>0; w>>=1){ if (t < w) sh[t] += sh[t+w]; __syncthreads(); }
    if (t==0) out[blockIdx.x] = sh[0] * (1.0f/9.0f);
}

// ---------------- launch ----------------
extern "C" void kernel_launch(void* const* d_in, const int* in_sizes, int n_in,
                              void* d_out, int out_size){
    const float* x_amp  = (const float*)d_in[0];
    const float* pnoise = (const float*)d_in[1];
    const float* amp    = (const float*)d_in[2];
    const float* phs    = (const float*)d_in[3];
    const float* mask   = (const float*)d_in[4];
    float* out = (float*)d_out;

    k_tw  <<<1,   512>>>();
    k_init<<<512, 512>>>(amp, phs, mask);

    // pipelined schedule: launch i runs pass (i-g) of group g for all valid g
    for (int i = 0; i < NG + 6; i++){
        int gmin = (i > 6) ? (i - 6) : 0;
        int gmax = (i < NG-1) ? i : (NG-1);
        int ns = gmax - gmin + 1;
        mega<<<ns*BPS, 256>>>(i, gmin, x_amp, pnoise);
    }
    redB<<<160, 64>>>(out);
}

// round 10
// speedup vs baseline: 1.2036x; 1.1005x over previous
#include <cuda_runtime.h>
#include <cuda_fp16.h>

#define PI_D 3.14159265358979323846
#define NN   512
#define N2   262144
#define NIMG 144
#define GSIZE 24          // images per pipeline group
#define NG    6           // number of groups
#define BPS   (GSIZE*64)  // blocks per pass-slice = 1536
#define RSTRIDE 584       // row kernels: warp stays within one region
#define CSTRIDE 578       // col kernels: conflict-free across regions
#define TWSZ   584        // skewed twiddle table (max SK(511)=574)
#define SK(i) ((i) + ((i)>>3))

// ---------------- device scratch (no allocations allowed) ----------------
static __device__ __half2 d_field[(size_t)NIMG*N2]; // ~151 MB, fp16 inter-pass field
static __device__ float2 d_Tl[3*N2];                 // layer transmissions
static __device__ float2 d_Hb[N2];                   // H / N^2
static __device__ float2 d_Hb2[N2];                  // H^2 / N^2
static __device__ float2 d_tw[NN];                   // e^{-2pi i k/512}
static __device__ unsigned char d_cls[N2];           // pixel -> class (255 = none)
static __device__ float d_part[NIMG*64*10];          // per-block class partials

__device__ __forceinline__ float2 cmul(float2 a, float2 b){
    return make_float2(a.x*b.x - a.y*b.y, a.x*b.y + a.y*b.x);
}
__device__ __forceinline__ float2 h2f(__half2 h){ return __half22float2(h); }
__device__ __forceinline__ __half2 f2h(float2 f){ return __float22half2_rn(f); }

#define BREV_DECL const int brev[8] = {0,4,2,6,1,5,3,7}

// ---------------- radix-8 butterfly (DIF, output bit-reversed) ----------------
template<bool INV>
__device__ __forceinline__ void fft8(float2 v[8]){
    const float C0 = 0.70710678118654752440f;
    float2 t;
#define BTF(a,b) { t = a; a.x = t.x + b.x; a.y = t.y + b.y; b.x = t.x - b.x; b.y = t.y - b.y; }
    BTF(v[0],v[4]); BTF(v[1],v[5]); BTF(v[2],v[6]); BTF(v[3],v[7]);
    if (INV){
        v[5] = cmul(v[5], make_float2(C0,  C0));
        v[6] = make_float2(-v[6].y,  v[6].x);
        v[7] = cmul(v[7], make_float2(-C0, C0));
    } else {
        v[5] = cmul(v[5], make_float2(C0, -C0));
        v[6] = make_float2( v[6].y, -v[6].x);
        v[7] = cmul(v[7], make_float2(-C0,-C0));
    }
    BTF(v[0],v[2]); BTF(v[1],v[3]); BTF(v[4],v[6]); BTF(v[5],v[7]);
    if (INV){ v[3] = make_float2(-v[3].y, v[3].x); v[7] = make_float2(-v[7].y, v[7].x); }
    else    { v[3] = make_float2( v[3].y,-v[3].x); v[7] = make_float2( v[7].y,-v[7].x); }
    BTF(v[0],v[1]); BTF(v[2],v[3]); BTF(v[4],v[5]); BTF(v[6],v[7]);
#undef BTF
}

// apply brev permutation in registers (pure renaming, elided by ptxas)
__device__ __forceinline__ void permute_brev(float2 v[8]){
    BREV_DECL;
    float2 t[8];
#pragma unroll
    for (int r=0;r<8;r++) t[r] = v[brev[r]];
#pragma unroll
    for (int r=0;r<8;r++) v[r] = t[r];
}

// NOTE: twiddle table tw[] is stored SKEWED: logical tw[k] lives at tw[SK(k)].

// ---- dual-slot 512-pt FFT, ONE line, thread owns slots j and j+32 (j in 0..31)
template<bool INV, bool PERM>
__device__ __forceinline__ void fft512_dual(float2 v[8], float2 w[8],
                                            float2* s, int j, const float2* tw){
    BREV_DECL;
    if (PERM){ permute_brev(v); permute_brev(w); }
    fft8<INV>(v); fft8<INV>(w);
#pragma unroll
    for (int r=0;r<8;r++){ s[SK(8*j+r)] = v[brev[r]]; s[SK(8*(j+32)+r)] = w[brev[r]]; }
    __syncthreads();
#pragma unroll
    for (int r=0;r<8;r++){ v[r] = s[SK(j+64*r)]; w[r] = s[SK(j+32+64*r)]; }
    int jm = j & 7;
#pragma unroll
    for (int r=1;r<8;r++){
        float2 q = tw[SK(r*jm*8)];
        if (INV) q.y = -q.y;
        v[r] = cmul(v[r], q); w[r] = cmul(w[r], q);   // (j+32)&7 == j&7
    }
    fft8<INV>(v); fft8<INV>(w);
    int iv = ((j - jm) << 3) + jm;
    int iw = iv + 256;
    __syncthreads();
#pragma unroll
    for (int r=0;r<8;r++){ s[SK(iv + 8*r)] = v[brev[r]]; s[SK(iw + 8*r)] = w[brev[r]]; }
    __syncthreads();
#pragma unroll
    for (int r=0;r<8;r++){ v[r] = s[SK(j+64*r)]; w[r] = s[SK(j+32+64*r)]; }
#pragma unroll
    for (int r=1;r<8;r++){
        float2 qv = tw[SK(r*j)], qw = tw[SK(r*(j+32))];
        if (INV){ qv.y = -qv.y; qw.y = -qw.y; }
        v[r] = cmul(v[r], qv); w[r] = cmul(w[r], qw);
    }
    fft8<INV>(v); fft8<INV>(w);
}

// ---- dual-line 512-pt FFT: TWO independent lines (regions sA, sB), slot j (0..63)
template<bool INV, bool PERM>
__device__ __forceinline__ void fft512_dual2(float2 v[8], float2 w[8],
                                             float2* sA, float2* sB, int j,
                                             const float2* tw){
    BREV_DECL;
    if (PERM){ permute_brev(v); permute_brev(w); }
    fft8<INV>(v); fft8<INV>(w);
#pragma unroll
    for (int r=0;r<8;r++){ sA[SK(8*j+r)] = v[brev[r]]; sB[SK(8*j+r)] = w[brev[r]]; }
    __syncthreads();
#pragma unroll
    for (int r=0;r<8;r++){ v[r] = sA[SK(j+64*r)]; w[r] = sB[SK(j+64*r)]; }
    int jm = j & 7;
#pragma unroll
    for (int r=1;r<8;r++){
        float2 q = tw[SK(r*jm*8)];
        if (INV) q.y = -q.y;
        v[r] = cmul(v[r], q); w[r] = cmul(w[r], q);
    }
    fft8<INV>(v); fft8<INV>(w);
    int idxD = ((j - jm) << 3) + jm;
    __syncthreads();
#pragma unroll
    for (int r=0;r<8;r++){ sA[SK(idxD + 8*r)] = v[brev[r]]; sB[SK(idxD + 8*r)] = w[brev[r]]; }
    __syncthreads();
#pragma unroll
    for (int r=0;r<8;r++){ v[r] = sA[SK(j+64*r)]; w[r] = sB[SK(j+64*r)]; }
#pragma unroll
    for (int r=1;r<8;r++){
        float2 q = tw[SK(r*j)];
        if (INV) q.y = -q.y;
        v[r] = cmul(v[r], q); w[r] = cmul(w[r], q);
    }
    fft8<INV>(v); fft8<INV>(w);
}

// ---------------- init kernels ----------------
__global__ void k_tw(){
    int t = threadIdx.x;
    double ang = -2.0*PI_D*(double)t/512.0;
    d_tw[t] = make_float2((float)cos(ang), (float)sin(ang));
}

__global__ void k_init(const float* __restrict__ amp, const float* __restrict__ phs,
                       const float* __restrict__ mask){
    int i = blockIdx.x, j = threadIdx.x;
    int idx = i*NN + j;
    float inv = 1.0f/(512.0f*8e-6f);
    float fx = (float)(i<256 ? i : i-512) * inv;
    float fy = (float)(j<256 ? j : j-512) * inv;
    const float lam = 5.32e-7f;
    float lx = lam*fx, ly = lam*fy;
    float arg = 1.0f - lx*lx - ly*ly;
    float sa = sqrtf(fmaxf(arg, 0.0f));
    const float KZ = (float)(2.0*PI_D/5.32e-7*0.05);
    float phi = KZ * sa;                   // f32 rounding, matches jax path
    double s, c;
    sincos((double)phi, &s, &c);           // accurate for huge args
    float hr = (float)c, hi = (float)s;
    const float sc = 1.0f/262144.0f;
    d_Hb [idx] = make_float2(hr*sc, hi*sc);
    d_Hb2[idx] = make_float2((hr*hr - hi*hi)*sc, 2.0f*hr*hi*sc);
#pragma unroll
    for (int l=0;l<3;l++){
        float a = amp[l*N2+idx], p = phs[l*N2+idx];
        float sn, cs; sincosf(p, &sn, &cs);
        d_Tl[l*N2+idx] = make_float2(a*cs, a*sn);
    }
    unsigned char cl = 255;
#pragma unroll
    for (int q=0;q<10;q++) if (mask[q*N2 + idx] > 0.5f) cl = (unsigned char)q;
    d_cls[idx] = cl;
}

// ---------------- pass bodies (device functions) ----------------

__device__ __forceinline__ void body_p1(float2* S, float2* TW,
                                        const float* __restrict__ xamp,
                                        const float* __restrict__ pn,
                                        int inner, int img0){
    int t = threadIdx.x;
    int line = t >> 5, j = t & 31;
    int img  = img0 + (inner >> 6);
    int row  = ((inner & 63) << 3) + line;
    int b = img & 15, m = img >> 4;
    float fm = 0.5f * (float)(m+1);
    size_t ibase = (size_t)img*N2 + (size_t)row*NN;
    size_t bbase = (size_t)b  *N2 + (size_t)row*NN;
    float2 v[8], w[8];
#pragma unroll
    for (int r=0;r<8;r++){
        int e1 = j + 64*r, e2 = j + 32 + 64*r;
        float p1v = pn[ibase + e1], p2v = pn[ibase + e2];
        float x1 = xamp[bbase + e1], x2 = xamp[bbase + e2];
        float sn, cs;
        __sincosf(p1v*fm, &sn, &cs);
        float2 a = make_float2(x1*cs, x1*sn);
        v[r] = cmul(a, d_Tl[row*NN + e1]);
        __sincosf(p2v*fm, &sn, &cs);
        float2 bb = make_float2(x2*cs, x2*sn);
        w[r] = cmul(bb, d_Tl[row*NN + e2]);
    }
    fft512_dual<false,false>(v, w, S + line*RSTRIDE, j, TW);
    BREV_DECL;
#pragma unroll
    for (int r=0;r<8;r++){
        d_field[ibase + j + 64*r]      = f2h(v[brev[r]]);
        d_field[ibase + j + 32 + 64*r] = f2h(w[brev[r]]);
    }
}

__device__ __forceinline__ void body_col(float2* S, float2* TW,
                                         const float2* __restrict__ Hm,
                                         int inner, int img0){
    int t = threadIdx.x;
    int p = t & 3, j = t >> 2;          // pair id, slot
    int img = img0 + (inner >> 6);
    int colA = ((inner & 63) << 3) + 2*p;
    size_t ibase = (size_t)img*N2;
    BREV_DECL;
    float2 v[8], w[8];
#pragma unroll
    for (int r=0;r<8;r++){
        uint2 U = *(const uint2*)&d_field[ibase + (size_t)(j+64*r)*NN + colA];
        v[r] = h2f(*(__half2*)&U.x);
        w[r] = h2f(*(__half2*)&U.y);
    }
    float2* sA = S + (2*p  )*CSTRIDE;
    float2* sB = S + (2*p+1)*CSTRIDE;
    fft512_dual2<false,false>(v, w, sA, sB, j, TW);
    // in-place spectral multiply: v[i] holds elem j+64*brev[i]
#pragma unroll
    for (int i=0;i<8;i++){
        float4 Hp = *(const float4*)&Hm[(j+64*brev[i])*NN + colA];
        v[i] = cmul(v[i], make_float2(Hp.x, Hp.y));
        w[i] = cmul(w[i], make_float2(Hp.z, Hp.w));
    }
    __syncthreads();    // S free for second FFT
    fft512_dual2<true,true>(v, w, sA, sB, j, TW);
#pragma unroll
    for (int r=0;r<8;r++){
        uint2 U;
        *(__half2*)&U.x = f2h(v[brev[r]]);
        *(__half2*)&U.y = f2h(w[brev[r]]);
        *(uint2*)&d_field[ibase + (size_t)(j+64*r)*NN + colA] = U;
    }
}

__device__ __forceinline__ void body_mid(float2* S, float2* TW, int l,
                                         int inner, int img0){
    int t = threadIdx.x;
    int line = t >> 5, j = t & 31;
    int img  = img0 + (inner >> 6);
    int row  = ((inner & 63) << 3) + line;
    size_t ibase = (size_t)img*N2 + (size_t)row*NN;
    BREV_DECL;
    float2 v[8], w[8];
#pragma unroll
    for (int r=0;r<8;r++){
        v[r] = h2f(d_field[ibase + j + 64*r]);
        w[r] = h2f(d_field[ibase + j + 32 + 64*r]);
    }
    float2* s = S + line*RSTRIDE;
    fft512_dual<true,false>(v, w, s, j, TW);
    const float2* __restrict__ T = d_Tl + l*N2 + row*NN;
#pragma unroll
    for (int i=0;i<8;i++){
        v[i] = cmul(v[i], T[j + 64*brev[i]]);
        w[i] = cmul(w[i], T[j + 32 + 64*brev[i]]);
    }
    __syncthreads();
    fft512_dual<false,true>(v, w, s, j, TW);
#pragma unroll
    for (int r=0;r<8;r++){
        d_field[ibase + j + 64*r]      = f2h(v[brev[r]]);
        d_field[ibase + j + 32 + 64*r] = f2h(w[brev[r]]);
    }
}

__device__ __forceinline__ void body_p7(float2* S, float2* TW, float (*WP)[10],
                                        int inner, int img0){
    int t = threadIdx.x;
    int line = t >> 5, j = t & 31;
    int img  = img0 + (inner >> 6);
    int chunk = inner & 63;
    int row  = (chunk << 3) + line;
    size_t ibase = (size_t)img*N2 + (size_t)row*NN;
    BREV_DECL;
    float2 v[8], w[8];
#pragma unroll
    for (int r=0;r<8;r++){
        v[r] = h2f(d_field[ibase + j + 64*r]);
        w[r] = h2f(d_field[ibase + j + 32 + 64*r]);
    }
    fft512_dual<true,false>(v, w, S + line*RSTRIDE, j, TW);

    float acc[10];
#pragma unroll
    for (int q=0;q<10;q++) acc[q] = 0.f;
#pragma unroll
    for (int i=0;i<8;i++){
        float2 f = v[i];
        float I = f.x*f.x + f.y*f.y;
        int cl = d_cls[row*NN + j + 64*brev[i]];
#pragma unroll
        for (int q=0;q<10;q++) if (cl==q) acc[q] += I;
        f = w[i];
        I = f.x*f.x + f.y*f.y;
        cl = d_cls[row*NN + j + 32 + 64*brev[i]];
#pragma unroll
        for (int q=0;q<10;q++) if (cl==q) acc[q] += I;
    }
#pragma unroll
    for (int q=0;q<10;q++){
#pragma unroll
        for (int o=16;o>0;o>>=1)
            acc[q] += __shfl_xor_sync(0xffffffffu, acc[q], o);
    }
    if (j == 0){
#pragma unroll
        for (int q=0;q<10;q++) WP[line][q] = acc[q];
    }
    __syncthreads();
    if (t < 10){
        float s = 0.f;
#pragma unroll
        for (int q=0;q<8;q++) s += WP[q][t];
        d_part[(img*64 + chunk)*10 + t] = s;
    }
}

// ---------------- mega kernel: software-pipelined pass dispatch ----------------
__global__ void __launch_bounds__(256,4) mega(int i, int gmin,
                                              const float* __restrict__ xamp,
                                              const float* __restrict__ pn){
    __shared__ float2 S[8*RSTRIDE];   // RSTRIDE >= CSTRIDE
    __shared__ float2 TW[TWSZ];       // skewed twiddle table
    __shared__ float WP[8][10];
    int t = threadIdx.x;
    TW[SK(t)] = d_tw[t]; TW[SK(t+256)] = d_tw[t+256];

    int slice = blockIdx.x / BPS;
    int inner = blockIdx.x - slice * BPS;
    int g = gmin + slice;
    int p = i - g;
    int img0 = g * GSIZE;

    switch (p){
        case 0: body_p1 (S, TW, xamp, pn, inner, img0); break;
        case 1: body_col(S, TW, d_Hb,  inner, img0); break;
        case 2: body_mid(S, TW, 1,     inner, img0); break;
        case 3: body_col(S, TW, d_Hb,  inner, img0); break;
        case 4: body_mid(S, TW, 2,     inner, img0); break;
        case 5: body_col(S, TW, d_Hb2, inner, img0); break;   // fused last two props
        default: body_p7(S, TW, WP,    inner, img0); break;
    }
}

// final: sum over 9 modes x 64 chunks, /9, scores [16,10]
__global__ void redB(float* __restrict__ out){
    __shared__ float sh[64];
    int t = threadIdx.x;
    int b = blockIdx.x / 10, c = blockIdx.x % 10;
    float s = 0.f;
#pragma unroll
    for (int m=0;m<9;m++)
        s += d_part[(((m*16+b) << 6) + t)*10 + c];
    sh[t] = s; __syncthreads();
    for (int w=32; w>0; w>>=1){ if (t < w) sh[t] += sh[t+w]; __syncthreads(); }
    if (t==0) out[blockIdx.x] = sh[0] * (1.0f/9.0f);
}

// ---------------- launch ----------------
extern "C" void kernel_launch(void* const* d_in, const int* in_sizes, int n_in,
                              void* d_out, int out_size){
    const float* x_amp  = (const float*)d_in[0];
    const float* pnoise = (const float*)d_in[1];
    const float* amp    = (const float*)d_in[2];
    const float* phs    = (const float*)d_in[3];
    const float* mask   = (const float*)d_in[4];
    float* out = (float*)d_out;

    k_tw  <<<1,   512>>>();
    k_init<<<512, 512>>>(amp, phs, mask);

    // pipelined schedule: launch i runs pass (i-g) of group g for all valid g
    for (int i = 0; i < NG + 6; i++){
        int gmin = (i > 6) ? (i - 6) : 0;
        int gmax = (i < NG-1) ? i : (NG-1);
        int ns = gmax - gmin + 1;
        mega<<<ns*BPS, 256>>>(i, gmin, x_amp, pnoise);
    }
    redB<<<160, 64>>>(out);
}

// round 11
// speedup vs baseline: 1.3596x; 1.1296x over previous
#include <cuda_runtime.h>
#include <cuda_fp16.h>

#define PI_D 3.14159265358979323846
#define NN   512
#define N2   262144
#define NIMG 144
#define GSIZE 24          // images per pipeline group
#define NG    6           // number of groups
#define BPS   (GSIZE*64)  // blocks per pass-slice = 1536
#define RSTRIDE 584       // row kernels (half2 units): warp stays within one region
#define CSTRIDE 580       // col kernels (half2 units): (2p*580)%32=8p -> conflict-free
#define TWSZ   584        // skewed twiddle table (float2, max SK(511)=574)
#define SK(i) ((i) + ((i)>>3))

// ---------------- device scratch (no allocations allowed) ----------------
static __device__ __half2 d_field[(size_t)NIMG*N2]; // ~151 MB, fp16 inter-pass field
static __device__ float2 d_Tl[3*N2];                 // layer transmissions
static __device__ float2 d_Hb[N2];                   // H / N^2
static __device__ float2 d_Hb2[N2];                  // H^2 / N^2
static __device__ float2 d_tw[NN];                   // e^{-2pi i k/512}
static __device__ unsigned char d_cls[N2];           // pixel -> class (255 = none)
static __device__ float d_part[NIMG*64*10];          // per-block class partials

__device__ __forceinline__ float2 cmul(float2 a, float2 b){
    return make_float2(a.x*b.x - a.y*b.y, a.x*b.y + a.y*b.x);
}
__device__ __forceinline__ float2 h2f(__half2 h){ return __half22float2(h); }
__device__ __forceinline__ __half2 f2h(float2 f){ return __float22half2_rn(f); }

#define BREV_DECL const int brev[8] = {0,4,2,6,1,5,3,7}

// ---------------- radix-8 butterfly (DIF, output bit-reversed) ----------------
template<bool INV>
__device__ __forceinline__ void fft8(float2 v[8]){
    const float C0 = 0.70710678118654752440f;
    float2 t;
#define BTF(a,b) { t = a; a.x = t.x + b.x; a.y = t.y + b.y; b.x = t.x - b.x; b.y = t.y - b.y; }
    BTF(v[0],v[4]); BTF(v[1],v[5]); BTF(v[2],v[6]); BTF(v[3],v[7]);
    if (INV){
        v[5] = cmul(v[5], make_float2(C0,  C0));
        v[6] = make_float2(-v[6].y,  v[6].x);
        v[7] = cmul(v[7], make_float2(-C0, C0));
    } else {
        v[5] = cmul(v[5], make_float2(C0, -C0));
        v[6] = make_float2( v[6].y, -v[6].x);
        v[7] = cmul(v[7], make_float2(-C0,-C0));
    }
    BTF(v[0],v[2]); BTF(v[1],v[3]); BTF(v[4],v[6]); BTF(v[5],v[7]);
    if (INV){ v[3] = make_float2(-v[3].y, v[3].x); v[7] = make_float2(-v[7].y, v[7].x); }
    else    { v[3] = make_float2( v[3].y,-v[3].x); v[7] = make_float2( v[7].y,-v[7].x); }
    BTF(v[0],v[1]); BTF(v[2],v[3]); BTF(v[4],v[5]); BTF(v[6],v[7]);
#undef BTF
}

// apply brev permutation in registers (pure renaming, elided by ptxas)
__device__ __forceinline__ void permute_brev(float2 v[8]){
    BREV_DECL;
    float2 t[8];
#pragma unroll
    for (int r=0;r<8;r++) t[r] = v[brev[r]];
#pragma unroll
    for (int r=0;r<8;r++) v[r] = t[r];
}

// NOTE: twiddle table tw[] is float2, stored SKEWED: tw[k] lives at tw[SK(k)].
// Mid-FFT exchanges go through smem in HALF precision (half2 = one complex, 4B):
// halves crossbar bytes; butterflies stay fp32 in registers.

// ---- dual-slot 512-pt FFT, ONE line, thread owns slots j and j+32 (j in 0..31)
template<bool INV, bool PERM>
__device__ __forceinline__ void fft512_dual(float2 v[8], float2 w[8],
                                            __half2* s, int j, const float2* tw){
    BREV_DECL;
    if (PERM){ permute_brev(v); permute_brev(w); }
    fft8<INV>(v); fft8<INV>(w);
#pragma unroll
    for (int r=0;r<8;r++){ s[SK(8*j+r)] = f2h(v[brev[r]]); s[SK(8*(j+32)+r)] = f2h(w[brev[r]]); }
    __syncthreads();
#pragma unroll
    for (int r=0;r<8;r++){ v[r] = h2f(s[SK(j+64*r)]); w[r] = h2f(s[SK(j+32+64*r)]); }
    int jm = j & 7;
#pragma unroll
    for (int r=1;r<8;r++){
        float2 q = tw[SK(r*jm*8)];
        if (INV) q.y = -q.y;
        v[r] = cmul(v[r], q); w[r] = cmul(w[r], q);   // (j+32)&7 == j&7
    }
    fft8<INV>(v); fft8<INV>(w);
    int iv = ((j - jm) << 3) + jm;
    int iw = iv + 256;
    __syncthreads();
#pragma unroll
    for (int r=0;r<8;r++){ s[SK(iv + 8*r)] = f2h(v[brev[r]]); s[SK(iw + 8*r)] = f2h(w[brev[r]]); }
    __syncthreads();
#pragma unroll
    for (int r=0;r<8;r++){ v[r] = h2f(s[SK(j+64*r)]); w[r] = h2f(s[SK(j+32+64*r)]); }
#pragma unroll
    for (int r=1;r<8;r++){
        float2 qv = tw[SK(r*j)], qw = tw[SK(r*(j+32))];
        if (INV){ qv.y = -qv.y; qw.y = -qw.y; }
        v[r] = cmul(v[r], qv); w[r] = cmul(w[r], qw);
    }
    fft8<INV>(v); fft8<INV>(w);
}

// ---- dual-line 512-pt FFT: TWO independent lines (regions sA, sB), slot j (0..63)
template<bool INV, bool PERM>
__device__ __forceinline__ void fft512_dual2(float2 v[8], float2 w[8],
                                             __half2* sA, __half2* sB, int j,
                                             const float2* tw){
    BREV_DECL;
    if (PERM){ permute_brev(v); permute_brev(w); }
    fft8<INV>(v); fft8<INV>(w);
#pragma unroll
    for (int r=0;r<8;r++){ sA[SK(8*j+r)] = f2h(v[brev[r]]); sB[SK(8*j+r)] = f2h(w[brev[r]]); }
    __syncthreads();
#pragma unroll
    for (int r=0;r<8;r++){ v[r] = h2f(sA[SK(j+64*r)]); w[r] = h2f(sB[SK(j+64*r)]); }
    int jm = j & 7;
#pragma unroll
    for (int r=1;r<8;r++){
        float2 q = tw[SK(r*jm*8)];
        if (INV) q.y = -q.y;
        v[r] = cmul(v[r], q); w[r] = cmul(w[r], q);
    }
    fft8<INV>(v); fft8<INV>(w);
    int idxD = ((j - jm) << 3) + jm;
    __syncthreads();
#pragma unroll
    for (int r=0;r<8;r++){ sA[SK(idxD + 8*r)] = f2h(v[brev[r]]); sB[SK(idxD + 8*r)] = f2h(w[brev[r]]); }
    __syncthreads();
#pragma unroll
    for (int r=0;r<8;r++){ v[r] = h2f(sA[SK(j+64*r)]); w[r] = h2f(sB[SK(j+64*r)]); }
#pragma unroll
    for (int r=1;r<8;r++){
        float2 q = tw[SK(r*j)];
        if (INV) q.y = -q.y;
        v[r] = cmul(v[r], q); w[r] = cmul(w[r], q);
    }
    fft8<INV>(v); fft8<INV>(w);
}

// ---------------- init kernels ----------------
__global__ void k_tw(){
    int t = threadIdx.x;
    double ang = -2.0*PI_D*(double)t/512.0;
    d_tw[t] = make_float2((float)cos(ang), (float)sin(ang));
}

__global__ void k_init(const float* __restrict__ amp, const float* __restrict__ phs,
                       const float* __restrict__ mask){
    int i = blockIdx.x, j = threadIdx.x;
    int idx = i*NN + j;
    float inv = 1.0f/(512.0f*8e-6f);
    float fx = (float)(i<256 ? i : i-512) * inv;
    float fy = (float)(j<256 ? j : j-512) * inv;
    const float lam = 5.32e-7f;
    float lx = lam*fx, ly = lam*fy;
    float arg = 1.0f - lx*lx - ly*ly;
    float sa = sqrtf(fmaxf(arg, 0.0f));
    const float KZ = (float)(2.0*PI_D/5.32e-7*0.05);
    float phi = KZ * sa;                   // f32 rounding, matches jax path
    double s, c;
    sincos((double)phi, &s, &c);           // accurate for huge args
    float hr = (float)c, hi = (float)s;
    const float sc = 1.0f/262144.0f;
    d_Hb [idx] = make_float2(hr*sc, hi*sc);
    d_Hb2[idx] = make_float2((hr*hr - hi*hi)*sc, 2.0f*hr*hi*sc);
#pragma unroll
    for (int l=0;l<3;l++){
        float a = amp[l*N2+idx], p = phs[l*N2+idx];
        float sn, cs; sincosf(p, &sn, &cs);
        d_Tl[l*N2+idx] = make_float2(a*cs, a*sn);
    }
    unsigned char cl = 255;
#pragma unroll
    for (int q=0;q<10;q++) if (mask[q*N2 + idx] > 0.5f) cl = (unsigned char)q;
    d_cls[idx] = cl;
}

// ---------------- pass bodies (device functions) ----------------

__device__ __forceinline__ void body_p1(__half2* S, float2* TW,
                                        const float* __restrict__ xamp,
                                        const float* __restrict__ pn,
                                        int inner, int img0){
    int t = threadIdx.x;
    int line = t >> 5, j = t & 31;
    int img  = img0 + (inner >> 6);
    int row  = ((inner & 63) << 3) + line;
    int b = img & 15, m = img >> 4;
    float fm = 0.5f * (float)(m+1);
    size_t ibase = (size_t)img*N2 + (size_t)row*NN;
    size_t bbase = (size_t)b  *N2 + (size_t)row*NN;
    float2 v[8], w[8];
#pragma unroll
    for (int r=0;r<8;r++){
        int e1 = j + 64*r, e2 = j + 32 + 64*r;
        float p1v = pn[ibase + e1], p2v = pn[ibase + e2];
        float x1 = xamp[bbase + e1], x2 = xamp[bbase + e2];
        float sn, cs;
        __sincosf(p1v*fm, &sn, &cs);
        float2 a = make_float2(x1*cs, x1*sn);
        v[r] = cmul(a, d_Tl[row*NN + e1]);
        __sincosf(p2v*fm, &sn, &cs);
        float2 bb = make_float2(x2*cs, x2*sn);
        w[r] = cmul(bb, d_Tl[row*NN + e2]);
    }
    fft512_dual<false,false>(v, w, S + line*RSTRIDE, j, TW);
    BREV_DECL;
#pragma unroll
    for (int r=0;r<8;r++){
        d_field[ibase + j + 64*r]      = f2h(v[brev[r]]);
        d_field[ibase + j + 32 + 64*r] = f2h(w[brev[r]]);
    }
}

__device__ __forceinline__ void body_col(__half2* S, float2* TW,
                                         const float2* __restrict__ Hm,
                                         int inner, int img0){
    int t = threadIdx.x;
    int p = t & 3, j = t >> 2;          // pair id, slot
    int img = img0 + (inner >> 6);
    int colA = ((inner & 63) << 3) + 2*p;
    size_t ibase = (size_t)img*N2;
    BREV_DECL;
    float2 v[8], w[8];
#pragma unroll
    for (int r=0;r<8;r++){
        uint2 U = *(const uint2*)&d_field[ibase + (size_t)(j+64*r)*NN + colA];
        v[r] = h2f(*(__half2*)&U.x);
        w[r] = h2f(*(__half2*)&U.y);
    }
    __half2* sA = S + (2*p  )*CSTRIDE;
    __half2* sB = S + (2*p+1)*CSTRIDE;
    fft512_dual2<false,false>(v, w, sA, sB, j, TW);
    // in-place spectral multiply: v[i] holds elem j+64*brev[i]
#pragma unroll
    for (int i=0;i<8;i++){
        float4 Hp = *(const float4*)&Hm[(j+64*brev[i])*NN + colA];
        v[i] = cmul(v[i], make_float2(Hp.x, Hp.y));
        w[i] = cmul(w[i], make_float2(Hp.z, Hp.w));
    }
    __syncthreads();    // S free for second FFT
    fft512_dual2<true,true>(v, w, sA, sB, j, TW);
#pragma unroll
    for (int r=0;r<8;r++){
        uint2 U;
        *(__half2*)&U.x = f2h(v[brev[r]]);
        *(__half2*)&U.y = f2h(w[brev[r]]);
        *(uint2*)&d_field[ibase + (size_t)(j+64*r)*NN + colA] = U;
    }
}

__device__ __forceinline__ void body_mid(__half2* S, float2* TW, int l,
                                         int inner, int img0){
    int t = threadIdx.x;
    int line = t >> 5, j = t & 31;
    int img  = img0 + (inner >> 6);
    int row  = ((inner & 63) << 3) + line;
    size_t ibase = (size_t)img*N2 + (size_t)row*NN;
    BREV_DECL;
    float2 v[8], w[8];
#pragma unroll
    for (int r=0;r<8;r++){
        v[r] = h2f(d_field[ibase + j + 64*r]);
        w[r] = h2f(d_field[ibase + j + 32 + 64*r]);
    }
    __half2* s = S + line*RSTRIDE;
    fft512_dual<true,false>(v, w, s, j, TW);
    const float2* __restrict__ T = d_Tl + l*N2 + row*NN;
#pragma unroll
    for (int i=0;i<8;i++){
        v[i] = cmul(v[i], T[j + 64*brev[i]]);
        w[i] = cmul(w[i], T[j + 32 + 64*brev[i]]);
    }
    __syncthreads();
    fft512_dual<false,true>(v, w, s, j, TW);
#pragma unroll
    for (int r=0;r<8;r++){
        d_field[ibase + j + 64*r]      = f2h(v[brev[r]]);
        d_field[ibase + j + 32 + 64*r] = f2h(w[brev[r]]);
    }
}

__device__ __forceinline__ void body_p7(__half2* S, float2* TW, float (*WP)[10],
                                        int inner, int img0){
    int t = threadIdx.x;
    int line = t >> 5, j = t & 31;
    int img  = img0 + (inner >> 6);
    int chunk = inner & 63;
    int row  = (chunk << 3) + line;
    size_t ibase = (size_t)img*N2 + (size_t)row*NN;
    BREV_DECL;
    float2 v[8], w[8];
#pragma unroll
    for (int r=0;r<8;r++){
        v[r] = h2f(d_field[ibase + j + 64*r]);
        w[r] = h2f(d_field[ibase + j + 32 + 64*r]);
    }
    fft512_dual<true,false>(v, w, S + line*RSTRIDE, j, TW);

    float acc[10];
#pragma unroll
    for (int q=0;q<10;q++) acc[q] = 0.f;
#pragma unroll
    for (int i=0;i<8;i++){
        float2 f = v[i];
        float I = f.x*f.x + f.y*f.y;
        int cl = d_cls[row*NN + j + 64*brev[i]];
#pragma unroll
        for (int q=0;q<10;q++) if (cl==q) acc[q] += I;
        f = w[i];
        I = f.x*f.x + f.y*f.y;
        cl = d_cls[row*NN + j + 32 + 64*brev[i]];
#pragma unroll
        for (int q=0;q<10;q++) if (cl==q) acc[q] += I;
    }
#pragma unroll
    for (int q=0;q<10;q++){
#pragma unroll
        for (int o=16;o>0;o>>=1)
            acc[q] += __shfl_xor_sync(0xffffffffu, acc[q], o);
    }
    if (j == 0){
#pragma unroll
        for (int q=0;q<10;q++) WP[line][q] = acc[q];
    }
    __syncthreads();
    if (t < 10){
        float s = 0.f;
#pragma unroll
        for (int q=0;q<8;q++) s += WP[q][t];
        d_part[(img*64 + chunk)*10 + t] = s;
    }
}

// ---------------- mega kernel: software-pipelined pass dispatch ----------------
__global__ void __launch_bounds__(256,4) mega(int i, int gmin,
                                              const float* __restrict__ xamp,
                                              const float* __restrict__ pn){
    __shared__ __half2 S[8*RSTRIDE];  // half-precision exchange buffer (~18.7KB)
    __shared__ float2 TW[TWSZ];       // skewed fp32 twiddle table
    __shared__ float WP[8][10];
    int t = threadIdx.x;
    TW[SK(t)] = d_tw[t]; TW[SK(t+256)] = d_tw[t+256];

    int slice = blockIdx.x / BPS;
    int inner = blockIdx.x - slice * BPS;
    int g = gmin + slice;
    int p = i - g;
    int img0 = g * GSIZE;

    switch (p){
        case 0: body_p1 (S, TW, xamp, pn, inner, img0); break;
        case 1: body_col(S, TW, d_Hb,  inner, img0); break;
        case 2: body_mid(S, TW, 1,     inner, img0); break;
        case 3: body_col(S, TW, d_Hb,  inner, img0); break;
        case 4: body_mid(S, TW, 2,     inner, img0); break;
        case 5: body_col(S, TW, d_Hb2, inner, img0); break;   // fused last two props
        default: body_p7(S, TW, WP,    inner, img0); break;
    }
}

// final: sum over 9 modes x 64 chunks, /9, scores [16,10]
__global__ void redB(float* __restrict__ out){
    __shared__ float sh[64];
    int t = threadIdx.x;
    int b = blockIdx.x / 10, c = blockIdx.x % 10;
    float s = 0.f;
#pragma unroll
    for (int m=0;m<9;m++)
        s += d_part[(((m*16+b) << 6) + t)*10 + c];
    sh[t] = s; __syncthreads();
    for (int w=32; w>0; w>>=1){ if (t < w) sh[t] += sh[t+w]; __syncthreads(); }
    if (t==0) out[blockIdx.x] = sh[0] * (1.0f/9.0f);
}

// ---------------- launch ----------------
extern "C" void kernel_launch(void* const* d_in, const int* in_sizes, int n_in,
                              void* d_out, int out_size){
    const float* x_amp  = (const float*)d_in[0];
    const float* pnoise = (const float*)d_in[1];
    const float* amp    = (const float*)d_in[2];
    const float* phs    = (const float*)d_in[3];
    const float* mask   = (const float*)d_in[4];
    float* out = (float*)d_out;

    k_tw  <<<1,   512>>>();
    k_init<<<512, 512>>>(amp, phs, mask);

    // pipelined schedule: launch i runs pass (i-g) of group g for all valid g
    for (int i = 0; i < NG + 6; i++){
        int gmin = (i > 6) ? (i - 6) : 0;
        int gmax = (i < NG-1) ? i : (NG-1);
        int ns = gmax - gmin + 1;
        mega<<<ns*BPS, 256>>>(i, gmin, x_amp, pnoise);
    }
    redB<<<160, 64>>>(out);
}

// round 12
// speedup vs baseline: 1.4110x; 1.0378x over previous
#include <cuda_runtime.h>
#include <cuda_fp16.h>

#define PI_D 3.14159265358979323846
#define NN   512
#define N2   262144
#define NIMG 144
#define GSIZE 24          // images per pipeline group
#define NG    6           // number of groups
#define BPS   (GSIZE*64)  // blocks per pass-slice = 1536
#define RSTRIDE 584       // row kernels (half2 units): warp stays within one region
#define CSTRIDE 580       // col kernels (half2 units): (2p*580)%32=8p -> conflict-free
#define TWSZ   584        // skewed twiddle table (float2, max SK(511)=574)
#define SK(i) ((i) + ((i)>>3))

typedef unsigned long long cplx;   // packed complex: lo=re, hi=im (f32x2 register pair)

// ---------------- device scratch (no allocations allowed) ----------------
static __device__ __half2 d_field[(size_t)NIMG*N2]; // ~151 MB, fp16 inter-pass field
static __device__ float2 d_Tl[3*N2];                 // layer transmissions
static __device__ float2 d_Hb[N2];                   // H / N^2
static __device__ float2 d_Hb2[N2];                  // H^2 / N^2
static __device__ float2 d_tw[NN];                   // e^{-2pi i k/512}
static __device__ unsigned char d_cls[N2];           // pixel -> class (255 = none)
static __device__ float d_part[NIMG*64*10];          // per-block class partials

// ---------------- packed-complex helpers ----------------
__device__ __forceinline__ cplx mkc(float x, float y){
    cplx r; asm("mov.b64 %0, {%1, %2};" : "=l"(r) : "f"(x), "f"(y)); return r;
}
__device__ __forceinline__ float2 c2f(cplx a){
    float2 f; asm("mov.b64 {%0, %1}, %2;" : "=f"(f.x), "=f"(f.y) : "l"(a)); return f;
}
__device__ __forceinline__ cplx cadd(cplx a, cplx b){
    cplx r; asm("add.rn.f32x2 %0, %1, %2;" : "=l"(r) : "l"(a), "l"(b)); return r;
}
__device__ __forceinline__ cplx csub(cplx a, cplx b){
    cplx r; asm("sub.rn.f32x2 %0, %1, %2;" : "=l"(r) : "l"(a), "l"(b)); return r;
}
// complex * complex (b as float2), scalar datapath
__device__ __forceinline__ cplx cmulf(cplx a, float2 b){
    float2 f = c2f(a);
    return mkc(f.x*b.x - f.y*b.y, f.x*b.y + f.y*b.x);
}
// complex * conj(b)
__device__ __forceinline__ cplx cmulcf(cplx a, float2 b){
    float2 f = c2f(a);
    return mkc(f.x*b.x + f.y*b.y, f.y*b.x - f.x*b.y);
}
__device__ __forceinline__ __half2 c2h(cplx a){
    float2 f = c2f(a); return __float22half2_rn(f);
}
__device__ __forceinline__ cplx h2c(__half2 h){
    float2 f = __half22float2(h); return mkc(f.x, f.y);
}

#define BREV_DECL const int brev[8] = {0,4,2,6,1,5,3,7}

// ---------------- radix-8 butterfly (DIF, output bit-reversed) ----------------
template<bool INV>
__device__ __forceinline__ void fft8(cplx v[8]){
    const float C0 = 0.70710678118654752440f;
#define BTF(a,b) { cplx s_ = cadd(a,b); b = csub(a,b); a = s_; }
    BTF(v[0],v[4]); BTF(v[1],v[5]); BTF(v[2],v[6]); BTF(v[3],v[7]);
    {   // v5 *= (C0, -+C0); v6 *= -+i; v7 *= (-C0, -+C0)
        float2 f5 = c2f(v[5]), f6 = c2f(v[6]), f7 = c2f(v[7]);
        if (INV){
            v[5] = mkc(C0*(f5.x - f5.y), C0*(f5.x + f5.y));
            v[6] = mkc(-f6.y, f6.x);
            v[7] = mkc(-C0*(f7.x + f7.y), C0*(f7.x - f7.y));
        } else {
            v[5] = mkc(C0*(f5.x + f5.y), C0*(f5.y - f5.x));
            v[6] = mkc(f6.y, -f6.x);
            v[7] = mkc(C0*(f7.y - f7.x), -C0*(f7.x + f7.y));
        }
    }
    BTF(v[0],v[2]); BTF(v[1],v[3]); BTF(v[4],v[6]); BTF(v[5],v[7]);
    {
        float2 f3 = c2f(v[3]), f7 = c2f(v[7]);
        if (INV){ v[3] = mkc(-f3.y, f3.x); v[7] = mkc(-f7.y, f7.x); }
        else    { v[3] = mkc(f3.y, -f3.x); v[7] = mkc(f7.y, -f7.x); }
    }
    BTF(v[0],v[1]); BTF(v[2],v[3]); BTF(v[4],v[5]); BTF(v[6],v[7]);
#undef BTF
}

// apply brev permutation in registers (pure renaming)
__device__ __forceinline__ void permute_brev(cplx v[8]){
    BREV_DECL;
    cplx t[8];
#pragma unroll
    for (int r=0;r<8;r++) t[r] = v[brev[r]];
#pragma unroll
    for (int r=0;r<8;r++) v[r] = t[r];
}

// twiddle apply: forward = cmul, inverse = conj-mul (no FNEG on table value)
template<bool INV>
__device__ __forceinline__ cplx twmul(cplx a, float2 q){
    return INV ? cmulcf(a, q) : cmulf(a, q);
}

// NOTE: twiddle table tw[] is float2, stored SKEWED: tw[k] lives at tw[SK(k)].
// Mid-FFT exchanges go through smem in HALF precision (half2 = one complex, 4B).

// ---- dual-slot 512-pt FFT, ONE line, thread owns slots j and j+32 (j in 0..31)
template<bool INV, bool PERM>
__device__ __forceinline__ void fft512_dual(cplx v[8], cplx w[8],
                                            __half2* s, int j, const float2* tw){
    BREV_DECL;
    if (PERM){ permute_brev(v); permute_brev(w); }
    fft8<INV>(v); fft8<INV>(w);
#pragma unroll
    for (int r=0;r<8;r++){ s[SK(8*j+r)] = c2h(v[brev[r]]); s[SK(8*(j+32)+r)] = c2h(w[brev[r]]); }
    __syncthreads();
#pragma unroll
    for (int r=0;r<8;r++){ v[r] = h2c(s[SK(j+64*r)]); w[r] = h2c(s[SK(j+32+64*r)]); }
    int jm = j & 7;
#pragma unroll
    for (int r=1;r<8;r++){
        float2 q = tw[SK(r*jm*8)];
        v[r] = twmul<INV>(v[r], q); w[r] = twmul<INV>(w[r], q);  // (j+32)&7 == j&7
    }
    fft8<INV>(v); fft8<INV>(w);
    int iv = ((j - jm) << 3) + jm;
    int iw = iv + 256;
    __syncthreads();
#pragma unroll
    for (int r=0;r<8;r++){ s[SK(iv + 8*r)] = c2h(v[brev[r]]); s[SK(iw + 8*r)] = c2h(w[brev[r]]); }
    __syncthreads();
#pragma unroll
    for (int r=0;r<8;r++){ v[r] = h2c(s[SK(j+64*r)]); w[r] = h2c(s[SK(j+32+64*r)]); }
#pragma unroll
    for (int r=1;r<8;r++){
        v[r] = twmul<INV>(v[r], tw[SK(r*j)]);
        w[r] = twmul<INV>(w[r], tw[SK(r*(j+32))]);
    }
    fft8<INV>(v); fft8<INV>(w);
}

// ---- dual-line 512-pt FFT: TWO independent lines (regions sA, sB), slot j (0..63)
template<bool INV, bool PERM>
__device__ __forceinline__ void fft512_dual2(cplx v[8], cplx w[8],
                                             __half2* sA, __half2* sB, int j,
                                             const float2* tw){
    BREV_DECL;
    if (PERM){ permute_brev(v); permute_brev(w); }
    fft8<INV>(v); fft8<INV>(w);
#pragma unroll
    for (int r=0;r<8;r++){ sA[SK(8*j+r)] = c2h(v[brev[r]]); sB[SK(8*j+r)] = c2h(w[brev[r]]); }
    __syncthreads();
#pragma unroll
    for (int r=0;r<8;r++){ v[r] = h2c(sA[SK(j+64*r)]); w[r] = h2c(sB[SK(j+64*r)]); }
    int jm = j & 7;
#pragma unroll
    for (int r=1;r<8;r++){
        float2 q = tw[SK(r*jm*8)];
        v[r] = twmul<INV>(v[r], q); w[r] = twmul<INV>(w[r], q);
    }
    fft8<INV>(v); fft8<INV>(w);
    int idxD = ((j - jm) << 3) + jm;
    __syncthreads();
#pragma unroll
    for (int r=0;r<8;r++){ sA[SK(idxD + 8*r)] = c2h(v[brev[r]]); sB[SK(idxD + 8*r)] = c2h(w[brev[r]]); }
    __syncthreads();
#pragma unroll
    for (int r=0;r<8;r++){ v[r] = h2c(sA[SK(j+64*r)]); w[r] = h2c(sB[SK(j+64*r)]); }
#pragma unroll
    for (int r=1;r<8;r++){
        float2 q = tw[SK(r*j)];
        v[r] = twmul<INV>(v[r], q); w[r] = twmul<INV>(w[r], q);
    }
    fft8<INV>(v); fft8<INV>(w);
}

// ---------------- init kernels ----------------
__global__ void k_tw(){
    int t = threadIdx.x;
    double ang = -2.0*PI_D*(double)t/512.0;
    d_tw[t] = make_float2((float)cos(ang), (float)sin(ang));
}

__global__ void k_init(const float* __restrict__ amp, const float* __restrict__ phs,
                       const float* __restrict__ mask){
    int i = blockIdx.x, j = threadIdx.x;
    int idx = i*NN + j;
    float inv = 1.0f/(512.0f*8e-6f);
    float fx = (float)(i<256 ? i : i-512) * inv;
    float fy = (float)(j<256 ? j : j-512) * inv;
    const float lam = 5.32e-7f;
    float lx = lam*fx, ly = lam*fy;
    float arg = 1.0f - lx*lx - ly*ly;
    float sa = sqrtf(fmaxf(arg, 0.0f));
    const float KZ = (float)(2.0*PI_D/5.32e-7*0.05);
    float phi = KZ * sa;                   // f32 rounding, matches jax path
    double s, c;
    sincos((double)phi, &s, &c);           // accurate for huge args
    float hr = (float)c, hi = (float)s;
    const float sc = 1.0f/262144.0f;
    d_Hb [idx] = make_float2(hr*sc, hi*sc);
    d_Hb2[idx] = make_float2((hr*hr - hi*hi)*sc, 2.0f*hr*hi*sc);
#pragma unroll
    for (int l=0;l<3;l++){
        float a = amp[l*N2+idx], p = phs[l*N2+idx];
        float sn, cs; sincosf(p, &sn, &cs);
        d_Tl[l*N2+idx] = make_float2(a*cs, a*sn);
    }
    unsigned char cl = 255;
#pragma unroll
    for (int q=0;q<10;q++) if (mask[q*N2 + idx] > 0.5f) cl = (unsigned char)q;
    d_cls[idx] = cl;
}

// ---------------- pass bodies (device functions) ----------------

__device__ __forceinline__ void body_p1(__half2* S, float2* TW,
                                        const float* __restrict__ xamp,
                                        const float* __restrict__ pn,
                                        int inner, int img0){
    int t = threadIdx.x;
    int line = t >> 5, j = t & 31;
    int img  = img0 + (inner >> 6);
    int row  = ((inner & 63) << 3) + line;
    int b = img & 15, m = img >> 4;
    float fm = 0.5f * (float)(m+1);
    size_t ibase = (size_t)img*N2 + (size_t)row*NN;
    size_t bbase = (size_t)b  *N2 + (size_t)row*NN;
    cplx v[8], w[8];
#pragma unroll
    for (int r=0;r<8;r++){
        int e1 = j + 64*r, e2 = j + 32 + 64*r;
        float p1v = pn[ibase + e1], p2v = pn[ibase + e2];
        float x1 = xamp[bbase + e1], x2 = xamp[bbase + e2];
        float sn, cs;
        __sincosf(p1v*fm, &sn, &cs);
        v[r] = cmulf(mkc(x1*cs, x1*sn), d_Tl[row*NN + e1]);
        __sincosf(p2v*fm, &sn, &cs);
        w[r] = cmulf(mkc(x2*cs, x2*sn), d_Tl[row*NN + e2]);
    }
    fft512_dual<false,false>(v, w, S + line*RSTRIDE, j, TW);
    BREV_DECL;
#pragma unroll
    for (int r=0;r<8;r++){
        d_field[ibase + j + 64*r]      = c2h(v[brev[r]]);
        d_field[ibase + j + 32 + 64*r] = c2h(w[brev[r]]);
    }
}

__device__ __forceinline__ void body_col(__half2* S, float2* TW,
                                         const float2* __restrict__ Hm,
                                         int inner, int img0){
    int t = threadIdx.x;
    int p = t & 3, j = t >> 2;          // pair id, slot
    int img = img0 + (inner >> 6);
    int colA = ((inner & 63) << 3) + 2*p;
    size_t ibase = (size_t)img*N2;
    BREV_DECL;
    cplx v[8], w[8];
#pragma unroll
    for (int r=0;r<8;r++){
        uint2 U = *(const uint2*)&d_field[ibase + (size_t)(j+64*r)*NN + colA];
        v[r] = h2c(*(__half2*)&U.x);
        w[r] = h2c(*(__half2*)&U.y);
    }
    __half2* sA = S + (2*p  )*CSTRIDE;
    __half2* sB = S + (2*p+1)*CSTRIDE;
    fft512_dual2<false,false>(v, w, sA, sB, j, TW);
    // in-place spectral multiply: v[i] holds elem j+64*brev[i]
#pragma unroll
    for (int i=0;i<8;i++){
        float4 Hp = *(const float4*)&Hm[(j+64*brev[i])*NN + colA];
        v[i] = cmulf(v[i], make_float2(Hp.x, Hp.y));
        w[i] = cmulf(w[i], make_float2(Hp.z, Hp.w));
    }
    __syncthreads();    // S free for second FFT
    fft512_dual2<true,true>(v, w, sA, sB, j, TW);
#pragma unroll
    for (int r=0;r<8;r++){
        uint2 U;
        *(__half2*)&U.x = c2h(v[brev[r]]);
        *(__half2*)&U.y = c2h(w[brev[r]]);
        *(uint2*)&d_field[ibase + (size_t)(j+64*r)*NN + colA] = U;
    }
}

__device__ __forceinline__ void body_mid(__half2* S, float2* TW, int l,
                                         int inner, int img0){
    int t = threadIdx.x;
    int line = t >> 5, j = t & 31;
    int img  = img0 + (inner >> 6);
    int row  = ((inner & 63) << 3) + line;
    size_t ibase = (size_t)img*N2 + (size_t)row*NN;
    BREV_DECL;
    cplx v[8], w[8];
#pragma unroll
    for (int r=0;r<8;r++){
        v[r] = h2c(d_field[ibase + j + 64*r]);
        w[r] = h2c(d_field[ibase + j + 32 + 64*r]);
    }
    __half2* s = S + line*RSTRIDE;
    fft512_dual<true,false>(v, w, s, j, TW);
    const float2* __restrict__ T = d_Tl + l*N2 + row*NN;
#pragma unroll
    for (int i=0;i<8;i++){
        v[i] = cmulf(v[i], T[j + 64*brev[i]]);
        w[i] = cmulf(w[i], T[j + 32 + 64*brev[i]]);
    }
    __syncthreads();
    fft512_dual<false,true>(v, w, s, j, TW);
#pragma unroll
    for (int r=0;r<8;r++){
        d_field[ibase + j + 64*r]      = c2h(v[brev[r]]);
        d_field[ibase + j + 32 + 64*r] = c2h(w[brev[r]]);
    }
}

__device__ __forceinline__ void body_p7(__half2* S, float2* TW, float (*WP)[10],
                                        int inner, int img0){
    int t = threadIdx.x;
    int line = t >> 5, j = t & 31;
    int img  = img0 + (inner >> 6);
    int chunk = inner & 63;
    int row  = (chunk << 3) + line;
    size_t ibase = (size_t)img*N2 + (size_t)row*NN;
    BREV_DECL;
    cplx v[8], w[8];
#pragma unroll
    for (int r=0;r<8;r++){
        v[r] = h2c(d_field[ibase + j + 64*r]);
        w[r] = h2c(d_field[ibase + j + 32 + 64*r]);
    }
    fft512_dual<true,false>(v, w, S + line*RSTRIDE, j, TW);

    float acc[10];
#pragma unroll
    for (int q=0;q<10;q++) acc[q] = 0.f;
#pragma unroll
    for (int i=0;i<8;i++){
        float2 f = c2f(v[i]);
        float I = f.x*f.x + f.y*f.y;
        int cl = d_cls[row*NN + j + 64*brev[i]];
#pragma unroll
        for (int q=0;q<10;q++) if (cl==q) acc[q] += I;
        f = c2f(w[i]);
        I = f.x*f.x + f.y*f.y;
        cl = d_cls[row*NN + j + 32 + 64*brev[i]];
#pragma unroll
        for (int q=0;q<10;q++) if (cl==q) acc[q] += I;
    }
#pragma unroll
    for (int q=0;q<10;q++){
#pragma unroll
        for (int o=16;o>0;o>>=1)
            acc[q] += __shfl_xor_sync(0xffffffffu, acc[q], o);
    }
    if (j == 0){
#pragma unroll
        for (int q=0;q<10;q++) WP[line][q] = acc[q];
    }
    __syncthreads();
    if (t < 10){
        float s = 0.f;
#pragma unroll
        for (int q=0;q<8;q++) s += WP[q][t];
        d_part[(img*64 + chunk)*10 + t] = s;
    }
}

// ---------------- mega kernel: software-pipelined pass dispatch ----------------
__global__ void __launch_bounds__(256,3) mega(int i, int gmin,
                                              const float* __restrict__ xamp,
                                              const float* __restrict__ pn){
    __shared__ __half2 S[8*RSTRIDE];  // half-precision exchange buffer (~18.7KB)
    __shared__ float2 TW[TWSZ];       // skewed fp32 twiddle table
    __shared__ float WP[8][10];
    int t = threadIdx.x;
    TW[SK(t)] = d_tw[t]; TW[SK(t+256)] = d_tw[t+256];

    int slice = blockIdx.x / BPS;
    int inner = blockIdx.x - slice * BPS;
    int g = gmin + slice;
    int p = i - g;
    int img0 = g * GSIZE;

    switch (p){
        case 0: body_p1 (S, TW, xamp, pn, inner, img0); break;
        case 1: body_col(S, TW, d_Hb,  inner, img0); break;
        case 2: body_mid(S, TW, 1,     inner, img0); break;
        case 3: body_col(S, TW, d_Hb,  inner, img0); break;
        case 4: body_mid(S, TW, 2,     inner, img0); break;
        case 5: body_col(S, TW, d_Hb2, inner, img0); break;   // fused last two props
        default: body_p7(S, TW, WP,    inner, img0); break;
    }
}

// final: sum over 9 modes x 64 chunks, /9, scores [16,10]
__global__ void redB(float* __restrict__ out){
    __shared__ float sh[64];
    int t = threadIdx.x;
    int b = blockIdx.x / 10, c = blockIdx.x % 10;
    float s = 0.f;
#pragma unroll
    for (int m=0;m<9;m++)
        s += d_part[(((m*16+b) << 6) + t)*10 + c];
    sh[t] = s; __syncthreads();
    for (int w=32; w>0; w>>=1){ if (t < w) sh[t] += sh[t+w]; __syncthreads(); }
    if (t==0) out[blockIdx.x] = sh[0] * (1.0f/9.0f);
}

// ---------------- launch ----------------
extern "C" void kernel_launch(void* const* d_in, const int* in_sizes, int n_in,
                              void* d_out, int out_size){
    const float* x_amp  = (const float*)d_in[0];
    const float* pnoise = (const float*)d_in[1];
    const float* amp    = (const float*)d_in[2];
    const float* phs    = (const float*)d_in[3];
    const float* mask   = (const float*)d_in[4];
    float* out = (float*)d_out;

    k_tw  <<<1,   512>>>();
    k_init<<<512, 512>>>(amp, phs, mask);

    // pipelined schedule: launch i runs pass (i-g) of group g for all valid g
    for (int i = 0; i < NG + 6; i++){
        int gmin = (i > 6) ? (i - 6) : 0;
        int gmax = (i < NG-1) ? i : (NG-1);
        int ns = gmax - gmin + 1;
        mega<<<ns*BPS, 256>>>(i, gmin, x_amp, pnoise);
    }
    redB<<<160, 64>>>(out);
}

// round 14
// speedup vs baseline: 1.4411x; 1.0213x over previous
#include <cuda_runtime.h>
#include <cuda_fp16.h>

#define PI_D 3.14159265358979323846
#define NN   512
#define N2   262144
#define NIMG 144
#define GSIZE 24          // images per pipeline group
#define NG    6           // number of groups
#define BPS   (GSIZE*64)  // blocks per pass-slice = 1536
#define RSTRIDE 584       // row kernels (half2 units): warp stays within one region
#define CSTRIDE 580       // col kernels (half2 units): (2p*580)%32=8p -> conflict-free
#define TWSZ   584        // skewed twiddle table (float2, max SK(511)=574)
#define SK(i) ((i) + ((i)>>3))

typedef unsigned long long cplx;   // packed complex: lo=re, hi=im (f32x2 register pair)

// ---------------- device scratch (no allocations allowed) ----------------
static __device__ __half2 d_field[(size_t)NIMG*N2]; // ~151 MB, fp16 inter-pass field
static __device__ float2 d_Tl[3*N2];                 // layer transmissions
static __device__ float2 d_Hb[N2];                   // H / N^2
static __device__ float2 d_Hb2[N2];                  // H^2 / N^2
static __device__ float2 d_tw[NN];                   // e^{-2pi i k/512}
static __device__ unsigned char d_cls[N2];           // pixel -> class (255 = none)
static __device__ float d_part[NIMG*64*10];          // per-block class partials

// ---------------- packed-complex helpers ----------------
__device__ __forceinline__ cplx mkc(float x, float y){
    cplx r; asm("mov.b64 %0, {%1, %2};" : "=l"(r) : "f"(x), "f"(y)); return r;
}
__device__ __forceinline__ float2 c2f(cplx a){
    float2 f; asm("mov.b64 {%0, %1}, %2;" : "=f"(f.x), "=f"(f.y) : "l"(a)); return f;
}
__device__ __forceinline__ cplx cadd(cplx a, cplx b){
    cplx r; asm("add.rn.f32x2 %0, %1, %2;" : "=l"(r) : "l"(a), "l"(b)); return r;
}
__device__ __forceinline__ cplx csub(cplx a, cplx b){
    cplx r; asm("sub.rn.f32x2 %0, %1, %2;" : "=l"(r) : "l"(a), "l"(b)); return r;
}
// complex * complex (b as float2), scalar datapath
__device__ __forceinline__ cplx cmulf(cplx a, float2 b){
    float2 f = c2f(a);
    return mkc(f.x*b.x - f.y*b.y, f.x*b.y + f.y*b.x);
}
// complex * conj(b)
__device__ __forceinline__ cplx cmulcf(cplx a, float2 b){
    float2 f = c2f(a);
    return mkc(f.x*b.x + f.y*b.y, f.y*b.x - f.x*b.y);
}
__device__ __forceinline__ __half2 c2h(cplx a){
    float2 f = c2f(a); return __float22half2_rn(f);
}
__device__ __forceinline__ cplx h2c(__half2 h){
    float2 f = __half22float2(h); return mkc(f.x, f.y);
}
// bit reinterpretation uint32 <-> half2
__device__ __forceinline__ __half2 u2h(unsigned int u){
    union { unsigned int u; __half2 h; } c; c.u = u; return c.h;
}
__device__ __forceinline__ unsigned int h2u(__half2 h){
    union { unsigned int u; __half2 h; } c; c.h = h; return c.u;
}

#define BREV_DECL const int brev[8] = {0,4,2,6,1,5,3,7}

// ---------------- radix-8 butterfly (DIF, output bit-reversed) ----------------
template<bool INV>
__device__ __forceinline__ void fft8(cplx v[8]){
    const float C0 = 0.70710678118654752440f;
#define BTF(a,b) { cplx s_ = cadd(a,b); b = csub(a,b); a = s_; }
    BTF(v[0],v[4]); BTF(v[1],v[5]); BTF(v[2],v[6]); BTF(v[3],v[7]);
    {   // v5 *= (C0, -+C0); v6 *= -+i; v7 *= (-C0, -+C0)
        float2 f5 = c2f(v[5]), f6 = c2f(v[6]), f7 = c2f(v[7]);
        if (INV){
            v[5] = mkc(C0*(f5.x - f5.y), C0*(f5.x + f5.y));
            v[6] = mkc(-f6.y, f6.x);
            v[7] = mkc(-C0*(f7.x + f7.y), C0*(f7.x - f7.y));
        } else {
            v[5] = mkc(C0*(f5.x + f5.y), C0*(f5.y - f5.x));
            v[6] = mkc(f6.y, -f6.x);
            v[7] = mkc(C0*(f7.y - f7.x), -C0*(f7.x + f7.y));
        }
    }
    BTF(v[0],v[2]); BTF(v[1],v[3]); BTF(v[4],v[6]); BTF(v[5],v[7]);
    {
        float2 f3 = c2f(v[3]), f7 = c2f(v[7]);
        if (INV){ v[3] = mkc(-f3.y, f3.x); v[7] = mkc(-f7.y, f7.x); }
        else    { v[3] = mkc(f3.y, -f3.x); v[7] = mkc(f7.y, -f7.x); }
    }
    BTF(v[0],v[1]); BTF(v[2],v[3]); BTF(v[4],v[5]); BTF(v[6],v[7]);
#undef BTF
}

// apply brev permutation in registers (pure renaming)
__device__ __forceinline__ void permute_brev(cplx v[8]){
    BREV_DECL;
    cplx t[8];
#pragma unroll
    for (int r=0;r<8;r++) t[r] = v[brev[r]];
#pragma unroll
    for (int r=0;r<8;r++) v[r] = t[r];
}

// twiddle apply: forward = cmul, inverse = conj-mul (no FNEG on table value)
template<bool INV>
__device__ __forceinline__ cplx twmul(cplx a, float2 q){
    return INV ? cmulcf(a, q) : cmulf(a, q);
}

// NOTE: twiddle table tw[] is float2, stored SKEWED: tw[k] lives at tw[SK(k)].
// Mid-FFT exchanges go through smem in HALF precision (half2 = one complex, 4B).
// Exchange phases store v's outputs BEFORE running w's butterfly to cut peak
// register liveness (targeting 64 regs / 4 CTAs).

// ---- dual-slot 512-pt FFT, ONE line, thread owns slots j and j+32 (j in 0..31)
template<bool INV, bool PERM>
__device__ __forceinline__ void fft512_dual(cplx v[8], cplx w[8],
                                            __half2* s, int j, const float2* tw){
    BREV_DECL;
    if (PERM){ permute_brev(v); permute_brev(w); }
    fft8<INV>(v);
#pragma unroll
    for (int r=0;r<8;r++) s[SK(8*j+r)] = c2h(v[brev[r]]);
    fft8<INV>(w);
#pragma unroll
    for (int r=0;r<8;r++) s[SK(8*(j+32)+r)] = c2h(w[brev[r]]);
    __syncthreads();
#pragma unroll
    for (int r=0;r<8;r++){ v[r] = h2c(s[SK(j+64*r)]); w[r] = h2c(s[SK(j+32+64*r)]); }
    int jm = j & 7;
#pragma unroll
    for (int r=1;r<8;r++){
        float2 q = tw[SK(r*jm*8)];
        v[r] = twmul<INV>(v[r], q); w[r] = twmul<INV>(w[r], q);  // (j+32)&7 == j&7
    }
    int iv = ((j - jm) << 3) + jm;
    __syncthreads();
    fft8<INV>(v);
#pragma unroll
    for (int r=0;r<8;r++) s[SK(iv + 8*r)] = c2h(v[brev[r]]);
    fft8<INV>(w);
#pragma unroll
    for (int r=0;r<8;r++) s[SK(iv + 256 + 8*r)] = c2h(w[brev[r]]);
    __syncthreads();
#pragma unroll
    for (int r=0;r<8;r++){ v[r] = h2c(s[SK(j+64*r)]); w[r] = h2c(s[SK(j+32+64*r)]); }
#pragma unroll
    for (int r=1;r<8;r++){
        v[r] = twmul<INV>(v[r], tw[SK(r*j)]);
        w[r] = twmul<INV>(w[r], tw[SK(r*(j+32))]);
    }
    fft8<INV>(v); fft8<INV>(w);
}

// ---- dual-line 512-pt FFT: TWO independent lines (regions sA, sB), slot j (0..63)
template<bool INV, bool PERM>
__device__ __forceinline__ void fft512_dual2(cplx v[8], cplx w[8],
                                             __half2* sA, __half2* sB, int j,
                                             const float2* tw){
    BREV_DECL;
    if (PERM){ permute_brev(v); permute_brev(w); }
    fft8<INV>(v);
#pragma unroll
    for (int r=0;r<8;r++) sA[SK(8*j+r)] = c2h(v[brev[r]]);
    fft8<INV>(w);
#pragma unroll
    for (int r=0;r<8;r++) sB[SK(8*j+r)] = c2h(w[brev[r]]);
    __syncthreads();
#pragma unroll
    for (int r=0;r<8;r++){ v[r] = h2c(sA[SK(j+64*r)]); w[r] = h2c(sB[SK(j+64*r)]); }
    int jm = j & 7;
#pragma unroll
    for (int r=1;r<8;r++){
        float2 q = tw[SK(r*jm*8)];
        v[r] = twmul<INV>(v[r], q); w[r] = twmul<INV>(w[r], q);
    }
    int idxD = ((j - jm) << 3) + jm;
    __syncthreads();
    fft8<INV>(v);
#pragma unroll
    for (int r=0;r<8;r++) sA[SK(idxD + 8*r)] = c2h(v[brev[r]]);
    fft8<INV>(w);
#pragma unroll
    for (int r=0;r<8;r++) sB[SK(idxD + 8*r)] = c2h(w[brev[r]]);
    __syncthreads();
#pragma unroll
    for (int r=0;r<8;r++){ v[r] = h2c(sA[SK(j+64*r)]); w[r] = h2c(sB[SK(j+64*r)]); }
#pragma unroll
    for (int r=1;r<8;r++){
        float2 q = tw[SK(r*j)];
        v[r] = twmul<INV>(v[r], q); w[r] = twmul<INV>(w[r], q);
    }
    fft8<INV>(v); fft8<INV>(w);
}

// ---------------- init kernels ----------------
__global__ void k_tw(){
    int t = threadIdx.x;
    double ang = -2.0*PI_D*(double)t/512.0;
    d_tw[t] = make_float2((float)cos(ang), (float)sin(ang));
}

__global__ void k_init(const float* __restrict__ amp, const float* __restrict__ phs,
                       const float* __restrict__ mask){
    int i = blockIdx.x, j = threadIdx.x;
    int idx = i*NN + j;
    float inv = 1.0f/(512.0f*8e-6f);
    float fx = (float)(i<256 ? i : i-512) * inv;
    float fy = (float)(j<256 ? j : j-512) * inv;
    const float lam = 5.32e-7f;
    float lx = lam*fx, ly = lam*fy;
    float arg = 1.0f - lx*lx - ly*ly;
    float sa = sqrtf(fmaxf(arg, 0.0f));
    const float KZ = (float)(2.0*PI_D/5.32e-7*0.05);
    float phi = KZ * sa;                   // f32 rounding, matches jax path
    double s, c;
    sincos((double)phi, &s, &c);           // accurate for huge args
    float hr = (float)c, hi = (float)s;
    const float sc = 1.0f/262144.0f;
    d_Hb [idx] = make_float2(hr*sc, hi*sc);
    d_Hb2[idx] = make_float2((hr*hr - hi*hi)*sc, 2.0f*hr*hi*sc);
#pragma unroll
    for (int l=0;l<3;l++){
        float a = amp[l*N2+idx], p = phs[l*N2+idx];
        float sn, cs; sincosf(p, &sn, &cs);
        d_Tl[l*N2+idx] = make_float2(a*cs, a*sn);
    }
    unsigned char cl = 255;
#pragma unroll
    for (int q=0;q<10;q++) if (mask[q*N2 + idx] > 0.5f) cl = (unsigned char)q;
    d_cls[idx] = cl;
}

// ---------------- pass bodies (device functions) ----------------

__device__ __forceinline__ void body_p1(__half2* S, float2* TW,
                                        const float* __restrict__ xamp,
                                        const float* __restrict__ pn,
                                        int inner, int img0){
    int t = threadIdx.x;
    int line = t >> 5, j = t & 31;
    int img  = img0 + (inner >> 6);
    int row  = ((inner & 63) << 3) + line;
    int b = img & 15, m = img >> 4;
    float fm = 0.5f * (float)(m+1);
    size_t ibase = (size_t)img*N2 + (size_t)row*NN;
    size_t bbase = (size_t)b  *N2 + (size_t)row*NN;
    cplx v[8], w[8];
#pragma unroll
    for (int r=0;r<8;r++){
        int e1 = j + 64*r, e2 = j + 32 + 64*r;
        float p1v = pn[ibase + e1], p2v = pn[ibase + e2];
        float x1 = xamp[bbase + e1], x2 = xamp[bbase + e2];
        float sn, cs;
        __sincosf(p1v*fm, &sn, &cs);
        v[r] = cmulf(mkc(x1*cs, x1*sn), d_Tl[row*NN + e1]);
        __sincosf(p2v*fm, &sn, &cs);
        w[r] = cmulf(mkc(x2*cs, x2*sn), d_Tl[row*NN + e2]);
    }
    fft512_dual<false,false>(v, w, S + line*RSTRIDE, j, TW);
    BREV_DECL;
#pragma unroll
    for (int r=0;r<8;r++){
        d_field[ibase + j + 64*r]      = c2h(v[brev[r]]);
        d_field[ibase + j + 32 + 64*r] = c2h(w[brev[r]]);
    }
}

__device__ __forceinline__ void body_col(__half2* S, float2* TW,
                                         const float2* __restrict__ Hm,
                                         int inner, int img0){
    int t = threadIdx.x;
    int p = t & 3, j = t >> 2;          // pair id, slot
    int img = img0 + (inner >> 6);
    int colA = ((inner & 63) << 3) + 2*p;
    size_t ibase = (size_t)img*N2;
    BREV_DECL;
    cplx v[8], w[8];
#pragma unroll
    for (int r=0;r<8;r++){
        uint2 U = *(const uint2*)&d_field[ibase + (size_t)(j+64*r)*NN + colA];
        v[r] = h2c(u2h(U.x));
        w[r] = h2c(u2h(U.y));
    }
    __half2* sA = S + (2*p  )*CSTRIDE;
    __half2* sB = S + (2*p+1)*CSTRIDE;
    fft512_dual2<false,false>(v, w, sA, sB, j, TW);
    // in-place spectral multiply: v[i] holds elem j+64*brev[i]
#pragma unroll
    for (int i=0;i<8;i++){
        float4 Hp = *(const float4*)&Hm[(j+64*brev[i])*NN + colA];
        v[i] = cmulf(v[i], make_float2(Hp.x, Hp.y));
        w[i] = cmulf(w[i], make_float2(Hp.z, Hp.w));
    }
    __syncthreads();    // S free for second FFT
    fft512_dual2<true,true>(v, w, sA, sB, j, TW);
#pragma unroll
    for (int r=0;r<8;r++){
        uint2 U;
        U.x = h2u(c2h(v[brev[r]]));
        U.y = h2u(c2h(w[brev[r]]));
        *(uint2*)&d_field[ibase + (size_t)(j+64*r)*NN + colA] = U;
    }
}

__device__ __forceinline__ void body_mid(__half2* S, float2* TW, int l,
                                         int inner, int img0){
    int t = threadIdx.x;
    int line = t >> 5, j = t & 31;
    int img  = img0 + (inner >> 6);
    int row  = ((inner & 63) << 3) + line;
    size_t ibase = (size_t)img*N2 + (size_t)row*NN;
    BREV_DECL;
    cplx v[8], w[8];
#pragma unroll
    for (int r=0;r<8;r++){
        v[r] = h2c(d_field[ibase + j + 64*r]);
        w[r] = h2c(d_field[ibase + j + 32 + 64*r]);
    }
    __half2* s = S + line*RSTRIDE;
    fft512_dual<true,false>(v, w, s, j, TW);
    const float2* __restrict__ T = d_Tl + l*N2 + row*NN;
#pragma unroll
    for (int i=0;i<8;i++){
        v[i] = cmulf(v[i], T[j + 64*brev[i]]);
        w[i] = cmulf(w[i], T[j + 32 + 64*brev[i]]);
    }
    __syncthreads();
    fft512_dual<false,true>(v, w, s, j, TW);
#pragma unroll
    for (int r=0;r<8;r++){
        d_field[ibase + j + 64*r]      = c2h(v[brev[r]]);
        d_field[ibase + j + 32 + 64*r] = c2h(w[brev[r]]);
    }
}

__device__ __forceinline__ void body_p7(__half2* S, float2* TW, float (*WP)[10],
                                        int inner, int img0){
    int t = threadIdx.x;
    int line = t >> 5, j = t & 31;
    int img  = img0 + (inner >> 6);
    int chunk = inner & 63;
    int row  = (chunk << 3) + line;
    size_t ibase = (size_t)img*N2 + (size_t)row*NN;
    BREV_DECL;
    cplx v[8], w[8];
#pragma unroll
    for (int r=0;r<8;r++){
        v[r] = h2c(d_field[ibase + j + 64*r]);
        w[r] = h2c(d_field[ibase + j + 32 + 64*r]);
    }
    fft512_dual<true,false>(v, w, S + line*RSTRIDE, j, TW);

    float acc[10];
#pragma unroll
    for (int q=0;q<10;q++) acc[q] = 0.f;
#pragma unroll
    for (int i=0;i<8;i++){
        float2 f = c2f(v[i]);
        float I = f.x*f.x + f.y*f.y;
        int cl = d_cls[row*NN + j + 64*brev[i]];
#pragma unroll
        for (int q=0;q<10;q++) if (cl==q) acc[q] += I;
        f = c2f(w[i]);
        I = f.x*f.x + f.y*f.y;
        cl = d_cls[row*NN + j + 32 + 64*brev[i]];
#pragma unroll
        for (int q=0;q<10;q++) if (cl==q) acc[q] += I;
    }
#pragma unroll
    for (int q=0;q<10;q++){
#pragma unroll
        for (int o=16;o>0;o>>=1)
            acc[q] += __shfl_xor_sync(0xffffffffu, acc[q], o);
    }
    if (j == 0){
#pragma unroll
        for (int q=0;q<10;q++) WP[line][q] = acc[q];
    }
    __syncthreads();
    if (t < 10){
        float s = 0.f;
#pragma unroll
        for (int q=0;q<8;q++) s += WP[q][t];
        d_part[(img*64 + chunk)*10 + t] = s;
    }
}

// ---------------- mega kernel: software-pipelined pass dispatch ----------------
__global__ void __launch_bounds__(256,4) mega(int i, int gmin,
                                              const float* __restrict__ xamp,
                                              const float* __restrict__ pn){
    __shared__ __half2 S[8*RSTRIDE];  // half-precision exchange buffer (~18.7KB)
    __shared__ float2 TW[TWSZ];       // skewed fp32 twiddle table
    __shared__ float WP[8][10];
    int t = threadIdx.x;
    TW[SK(t)] = d_tw[t]; TW[SK(t+256)] = d_tw[t+256];

    int slice = blockIdx.x / BPS;
    int inner = blockIdx.x - slice * BPS;
    int g = gmin + slice;
    int p = i - g;
    int img0 = g * GSIZE;

    switch (p){
        case 0: body_p1 (S, TW, xamp, pn, inner, img0); break;
        case 1: body_col(S, TW, d_Hb,  inner, img0); break;
        case 2: body_mid(S, TW, 1,     inner, img0); break;
        case 3: body_col(S, TW, d_Hb,  inner, img0); break;
        case 4: body_mid(S, TW, 2,     inner, img0); break;
        case 5: body_col(S, TW, d_Hb2, inner, img0); break;   // fused last two props
        default: body_p7(S, TW, WP,    inner, img0); break;
    }
}

// final: sum over 9 modes x 64 chunks, /9, scores [16,10]
__global__ void redB(float* __restrict__ out){
    __shared__ float sh[64];
    int t = threadIdx.x;
    int b = blockIdx.x / 10, c = blockIdx.x % 10;
    float s = 0.f;
#pragma unroll
    for (int m=0;m<9;m++)
        s += d_part[(((m*16+b) << 6) + t)*10 + c];
    sh[t] = s; __syncthreads();
    for (int w=32; w>0; w>>=1){ if (t < w) sh[t] += sh[t+w]; __syncthreads(); }
    if (t==0) out[blockIdx.x] = sh[0] * (1.0f/9.0f);
}

// ---------------- launch ----------------
extern "C" void kernel_launch(void* const* d_in, const int* in_sizes, int n_in,
                              void* d_out, int out_size){
    const float* x_amp  = (const float*)d_in[0];
    const float* pnoise = (const float*)d_in[1];
    const float* amp    = (const float*)d_in[2];
    const float* phs    = (const float*)d_in[3];
    const float* mask   = (const float*)d_in[4];
    float* out = (float*)d_out;

    k_tw  <<<1,   512>>>();
    k_init<<<512, 512>>>(amp, phs, mask);

    // pipelined schedule: launch i runs pass (i-g) of group g for all valid g
    for (int i = 0; i < NG + 6; i++){
        int gmin = (i > 6) ? (i - 6) : 0;
        int gmax = (i < NG-1) ? i : (NG-1);
        int ns = gmax - gmin + 1;
        mega<<<ns*BPS, 256>>>(i, gmin, x_amp, pnoise);
    }
    redB<<<160, 64>>>(out);
}

// round 15
// speedup vs baseline: 1.4626x; 1.0149x over previous
#include <cuda_runtime.h>
#include <cuda_fp16.h>

#define PI_D 3.14159265358979323846
#define NN   512
#define N2   262144
#define NIMG 144
#define GSIZE 24          // images per pipeline group
#define NG    6           // number of groups
#define BPS   (GSIZE*64)  // blocks per pass-slice = 1536
#define RSTRIDE 584       // row kernels (half2 units): warp-private region
#define CSTRIDE 580       // col kernels (half2 units): (2p*580)%32=8p -> conflict-free
#define TWSZ   584        // skewed twiddle table (float2, max SK(511)=574)
#define SK(i) ((i) + ((i)>>3))

typedef unsigned long long cplx;   // packed complex: lo=re, hi=im (f32x2 register pair)

// ---------------- device scratch (no allocations allowed) ----------------
static __device__ __half2 d_field[(size_t)NIMG*N2]; // ~151 MB, fp16 inter-pass field
static __device__ float2 d_Tl[3*N2];                 // layer transmissions
static __device__ float2 d_Hb[N2];                   // H / N^2
static __device__ float2 d_Hb2[N2];                  // H^2 / N^2
static __device__ float2 d_tw[NN];                   // e^{-2pi i k/512}
static __device__ unsigned char d_cls[N2];           // pixel -> class (255 = none)
static __device__ float d_part[NIMG*64*10];          // per-block class partials

// ---------------- packed-complex helpers ----------------
__device__ __forceinline__ cplx mkc(float x, float y){
    cplx r; asm("mov.b64 %0, {%1, %2};" : "=l"(r) : "f"(x), "f"(y)); return r;
}
__device__ __forceinline__ float2 c2f(cplx a){
    float2 f; asm("mov.b64 {%0, %1}, %2;" : "=f"(f.x), "=f"(f.y) : "l"(a)); return f;
}
__device__ __forceinline__ cplx cadd(cplx a, cplx b){
    cplx r; asm("add.rn.f32x2 %0, %1, %2;" : "=l"(r) : "l"(a), "l"(b)); return r;
}
__device__ __forceinline__ cplx csub(cplx a, cplx b){
    cplx r; asm("sub.rn.f32x2 %0, %1, %2;" : "=l"(r) : "l"(a), "l"(b)); return r;
}
// complex * complex (b as float2), scalar datapath
__device__ __forceinline__ cplx cmulf(cplx a, float2 b){
    float2 f = c2f(a);
    return mkc(f.x*b.x - f.y*b.y, f.x*b.y + f.y*b.x);
}
// complex * conj(b)
__device__ __forceinline__ cplx cmulcf(cplx a, float2 b){
    float2 f = c2f(a);
    return mkc(f.x*b.x + f.y*b.y, f.y*b.x - f.x*b.y);
}
__device__ __forceinline__ __half2 c2h(cplx a){
    float2 f = c2f(a); return __float22half2_rn(f);
}
__device__ __forceinline__ cplx h2c(__half2 h){
    float2 f = __half22float2(h); return mkc(f.x, f.y);
}
// bit reinterpretation uint32 <-> half2
__device__ __forceinline__ __half2 u2h(unsigned int u){
    union { unsigned int u; __half2 h; } c; c.u = u; return c.h;
}
__device__ __forceinline__ unsigned int h2u(__half2 h){
    union { unsigned int u; __half2 h; } c; c.h = h; return c.u;
}

#define BREV_DECL const int brev[8] = {0,4,2,6,1,5,3,7}

// ---------------- radix-8 butterfly (DIF, output bit-reversed) ----------------
template<bool INV>
__device__ __forceinline__ void fft8(cplx v[8]){
    const float C0 = 0.70710678118654752440f;
#define BTF(a,b) { cplx s_ = cadd(a,b); b = csub(a,b); a = s_; }
    BTF(v[0],v[4]); BTF(v[1],v[5]); BTF(v[2],v[6]); BTF(v[3],v[7]);
    {   // v5 *= (C0, -+C0); v6 *= -+i; v7 *= (-C0, -+C0)
        float2 f5 = c2f(v[5]), f6 = c2f(v[6]), f7 = c2f(v[7]);
        if (INV){
            v[5] = mkc(C0*(f5.x - f5.y), C0*(f5.x + f5.y));
            v[6] = mkc(-f6.y, f6.x);
            v[7] = mkc(-C0*(f7.x + f7.y), C0*(f7.x - f7.y));
        } else {
            v[5] = mkc(C0*(f5.x + f5.y), C0*(f5.y - f5.x));
            v[6] = mkc(f6.y, -f6.x);
            v[7] = mkc(C0*(f7.y - f7.x), -C0*(f7.x + f7.y));
        }
    }
    BTF(v[0],v[2]); BTF(v[1],v[3]); BTF(v[4],v[6]); BTF(v[5],v[7]);
    {
        float2 f3 = c2f(v[3]), f7 = c2f(v[7]);
        if (INV){ v[3] = mkc(-f3.y, f3.x); v[7] = mkc(-f7.y, f7.x); }
        else    { v[3] = mkc(f3.y, -f3.x); v[7] = mkc(f7.y, -f7.x); }
    }
    BTF(v[0],v[1]); BTF(v[2],v[3]); BTF(v[4],v[5]); BTF(v[6],v[7]);
#undef BTF
}

// apply brev permutation in registers (pure renaming)
__device__ __forceinline__ void permute_brev(cplx v[8]){
    BREV_DECL;
    cplx t[8];
#pragma unroll
    for (int r=0;r<8;r++) t[r] = v[brev[r]];
#pragma unroll
    for (int r=0;r<8;r++) v[r] = t[r];
}

// twiddle apply: forward = cmul, inverse = conj-mul (no FNEG on table value)
template<bool INV>
__device__ __forceinline__ cplx twmul(cplx a, float2 q){
    return INV ? cmulcf(a, q) : cmulf(a, q);
}

// NOTE: twiddle table tw[] is float2, stored SKEWED: tw[k] lives at tw[SK(k)].
// Mid-FFT exchanges go through smem in HALF precision (half2 = one complex, 4B).
// ROW FFT (fft512_dual): the whole line + its S region belong to ONE warp ->
// __syncwarp() is sufficient for the exchanges (caller provides one block-wide
// __syncthreads() after the TW table is loaded).

// ---- dual-slot 512-pt FFT, ONE line (warp-private), thread owns slots j, j+32
template<bool INV, bool PERM>
__device__ __forceinline__ void fft512_dual(cplx v[8], cplx w[8],
                                            __half2* s, int j, const float2* tw){
    BREV_DECL;
    if (PERM){ permute_brev(v); permute_brev(w); }
    fft8<INV>(v);
#pragma unroll
    for (int r=0;r<8;r++) s[SK(8*j+r)] = c2h(v[brev[r]]);
    fft8<INV>(w);
#pragma unroll
    for (int r=0;r<8;r++) s[SK(8*(j+32)+r)] = c2h(w[brev[r]]);
    __syncwarp();
#pragma unroll
    for (int r=0;r<8;r++){ v[r] = h2c(s[SK(j+64*r)]); w[r] = h2c(s[SK(j+32+64*r)]); }
    int jm = j & 7;
#pragma unroll
    for (int r=1;r<8;r++){
        float2 q = tw[SK(r*jm*8)];
        v[r] = twmul<INV>(v[r], q); w[r] = twmul<INV>(w[r], q);  // (j+32)&7 == j&7
    }
    int iv = ((j - jm) << 3) + jm;
    __syncwarp();
    fft8<INV>(v);
#pragma unroll
    for (int r=0;r<8;r++) s[SK(iv + 8*r)] = c2h(v[brev[r]]);
    fft8<INV>(w);
#pragma unroll
    for (int r=0;r<8;r++) s[SK(iv + 256 + 8*r)] = c2h(w[brev[r]]);
    __syncwarp();
#pragma unroll
    for (int r=0;r<8;r++){ v[r] = h2c(s[SK(j+64*r)]); w[r] = h2c(s[SK(j+32+64*r)]); }
#pragma unroll
    for (int r=1;r<8;r++){
        v[r] = twmul<INV>(v[r], tw[SK(r*j)]);
        w[r] = twmul<INV>(w[r], tw[SK(r*(j+32))]);
    }
    fft8<INV>(v); fft8<INV>(w);
}

// ---- dual-line 512-pt FFT: TWO independent lines (regions sA, sB), slot j (0..63)
// Regions span warps -> block-wide syncs required.
template<bool INV, bool PERM>
__device__ __forceinline__ void fft512_dual2(cplx v[8], cplx w[8],
                                             __half2* sA, __half2* sB, int j,
                                             const float2* tw){
    BREV_DECL;
    if (PERM){ permute_brev(v); permute_brev(w); }
    fft8<INV>(v);
#pragma unroll
    for (int r=0;r<8;r++) sA[SK(8*j+r)] = c2h(v[brev[r]]);
    fft8<INV>(w);
#pragma unroll
    for (int r=0;r<8;r++) sB[SK(8*j+r)] = c2h(w[brev[r]]);
    __syncthreads();
#pragma unroll
    for (int r=0;r<8;r++){ v[r] = h2c(sA[SK(j+64*r)]); w[r] = h2c(sB[SK(j+64*r)]); }
    int jm = j & 7;
#pragma unroll
    for (int r=1;r<8;r++){
        float2 q = tw[SK(r*jm*8)];
        v[r] = twmul<INV>(v[r], q); w[r] = twmul<INV>(w[r], q);
    }
    int idxD = ((j - jm) << 3) + jm;
    __syncthreads();
    fft8<INV>(v);
#pragma unroll
    for (int r=0;r<8;r++) sA[SK(idxD + 8*r)] = c2h(v[brev[r]]);
    fft8<INV>(w);
#pragma unroll
    for (int r=0;r<8;r++) sB[SK(idxD + 8*r)] = c2h(w[brev[r]]);
    __syncthreads();
#pragma unroll
    for (int r=0;r<8;r++){ v[r] = h2c(sA[SK(j+64*r)]); w[r] = h2c(sB[SK(j+64*r)]); }
#pragma unroll
    for (int r=1;r<8;r++){
        float2 q = tw[SK(r*j)];
        v[r] = twmul<INV>(v[r], q); w[r] = twmul<INV>(w[r], q);
    }
    fft8<INV>(v); fft8<INV>(w);
}

// ---------------- init kernels ----------------
__global__ void k_tw(){
    int t = threadIdx.x;
    double ang = -2.0*PI_D*(double)t/512.0;
    d_tw[t] = make_float2((float)cos(ang), (float)sin(ang));
}

__global__ void k_init(const float* __restrict__ amp, const float* __restrict__ phs,
                       const float* __restrict__ mask){
    int i = blockIdx.x, j = threadIdx.x;
    int idx = i*NN + j;
    float inv = 1.0f/(512.0f*8e-6f);
    float fx = (float)(i<256 ? i : i-512) * inv;
    float fy = (float)(j<256 ? j : j-512) * inv;
    const float lam = 5.32e-7f;
    float lx = lam*fx, ly = lam*fy;
    float arg = 1.0f - lx*lx - ly*ly;
    float sa = sqrtf(fmaxf(arg, 0.0f));
    const float KZ = (float)(2.0*PI_D/5.32e-7*0.05);
    float phi = KZ * sa;                   // f32 rounding, matches jax path
    double s, c;
    sincos((double)phi, &s, &c);           // accurate for huge args
    float hr = (float)c, hi = (float)s;
    const float sc = 1.0f/262144.0f;
    d_Hb [idx] = make_float2(hr*sc, hi*sc);
    d_Hb2[idx] = make_float2((hr*hr - hi*hi)*sc, 2.0f*hr*hi*sc);
#pragma unroll
    for (int l=0;l<3;l++){
        float a = amp[l*N2+idx], p = phs[l*N2+idx];
        float sn, cs; sincosf(p, &sn, &cs);
        d_Tl[l*N2+idx] = make_float2(a*cs, a*sn);
    }
    unsigned char cl = 255;
#pragma unroll
    for (int q=0;q<10;q++) if (mask[q*N2 + idx] > 0.5f) cl = (unsigned char)q;
    d_cls[idx] = cl;
}

// ---------------- pass bodies (device functions) ----------------

__device__ __forceinline__ void body_p1(__half2* S, float2* TW,
                                        const float* __restrict__ xamp,
                                        const float* __restrict__ pn,
                                        int inner, int img0){
    int t = threadIdx.x;
    int line = t >> 5, j = t & 31;
    int img  = img0 + (inner >> 6);
    int row  = ((inner & 63) << 3) + line;
    int b = img & 15, m = img >> 4;
    float fm = 0.5f * (float)(m+1);
    size_t ibase = (size_t)img*N2 + (size_t)row*NN;
    size_t bbase = (size_t)b  *N2 + (size_t)row*NN;
    cplx v[8], w[8];
#pragma unroll
    for (int r=0;r<8;r++){
        int e1 = j + 64*r, e2 = j + 32 + 64*r;
        float p1v = pn[ibase + e1], p2v = pn[ibase + e2];
        float x1 = xamp[bbase + e1], x2 = xamp[bbase + e2];
        float sn, cs;
        __sincosf(p1v*fm, &sn, &cs);
        v[r] = cmulf(mkc(x1*cs, x1*sn), d_Tl[row*NN + e1]);
        __sincosf(p2v*fm, &sn, &cs);
        w[r] = cmulf(mkc(x2*cs, x2*sn), d_Tl[row*NN + e2]);
    }
    fft512_dual<false,false>(v, w, S + line*RSTRIDE, j, TW);
    BREV_DECL;
#pragma unroll
    for (int r=0;r<8;r++){
        d_field[ibase + j + 64*r]      = c2h(v[brev[r]]);
        d_field[ibase + j + 32 + 64*r] = c2h(w[brev[r]]);
    }
}

__device__ __forceinline__ void body_col(__half2* S, float2* TW,
                                         const float2* __restrict__ Hm,
                                         int inner, int img0){
    int t = threadIdx.x;
    int p = t & 3, j = t >> 2;          // pair id, slot
    int img = img0 + (inner >> 6);
    int colA = ((inner & 63) << 3) + 2*p;
    size_t ibase = (size_t)img*N2;
    BREV_DECL;
    cplx v[8], w[8];
#pragma unroll
    for (int r=0;r<8;r++){
        uint2 U = *(const uint2*)&d_field[ibase + (size_t)(j+64*r)*NN + colA];
        v[r] = h2c(u2h(U.x));
        w[r] = h2c(u2h(U.y));
    }
    __half2* sA = S + (2*p  )*CSTRIDE;
    __half2* sB = S + (2*p+1)*CSTRIDE;
    fft512_dual2<false,false>(v, w, sA, sB, j, TW);
    // in-place spectral multiply: v[i] holds elem j+64*brev[i]
#pragma unroll
    for (int i=0;i<8;i++){
        float4 Hp = *(const float4*)&Hm[(j+64*brev[i])*NN + colA];
        v[i] = cmulf(v[i], make_float2(Hp.x, Hp.y));
        w[i] = cmulf(w[i], make_float2(Hp.z, Hp.w));
    }
    __syncthreads();    // S free for second FFT
    fft512_dual2<true,true>(v, w, sA, sB, j, TW);
#pragma unroll
    for (int r=0;r<8;r++){
        uint2 U;
        U.x = h2u(c2h(v[brev[r]]));
        U.y = h2u(c2h(w[brev[r]]));
        *(uint2*)&d_field[ibase + (size_t)(j+64*r)*NN + colA] = U;
    }
}

__device__ __forceinline__ void body_mid(__half2* S, float2* TW, int l,
                                         int inner, int img0){
    int t = threadIdx.x;
    int line = t >> 5, j = t & 31;
    int img  = img0 + (inner >> 6);
    int row  = ((inner & 63) << 3) + line;
    size_t ibase = (size_t)img*N2 + (size_t)row*NN;
    BREV_DECL;
    cplx v[8], w[8];
#pragma unroll
    for (int r=0;r<8;r++){
        v[r] = h2c(d_field[ibase + j + 64*r]);
        w[r] = h2c(d_field[ibase + j + 32 + 64*r]);
    }
    __half2* s = S + line*RSTRIDE;
    fft512_dual<true,false>(v, w, s, j, TW);
    const float2* __restrict__ T = d_Tl + l*N2 + row*NN;
#pragma unroll
    for (int i=0;i<8;i++){
        v[i] = cmulf(v[i], T[j + 64*brev[i]]);
        w[i] = cmulf(w[i], T[j + 32 + 64*brev[i]]);
    }
    __syncwarp();      // S region is warp-private
    fft512_dual<false,true>(v, w, s, j, TW);
#pragma unroll
    for (int r=0;r<8;r++){
        d_field[ibase + j + 64*r]      = c2h(v[brev[r]]);
        d_field[ibase + j + 32 + 64*r] = c2h(w[brev[r]]);
    }
}

__device__ __forceinline__ void body_p7(__half2* S, float2* TW, float (*WP)[10],
                                        int inner, int img0){
    int t = threadIdx.x;
    int line = t >> 5, j = t & 31;
    int img  = img0 + (inner >> 6);
    int chunk = inner & 63;
    int row  = (chunk << 3) + line;
    size_t ibase = (size_t)img*N2 + (size_t)row*NN;
    BREV_DECL;
    cplx v[8], w[8];
#pragma unroll
    for (int r=0;r<8;r++){
        v[r] = h2c(d_field[ibase + j + 64*r]);
        w[r] = h2c(d_field[ibase + j + 32 + 64*r]);
    }
    fft512_dual<true,false>(v, w, S + line*RSTRIDE, j, TW);

    float acc[10];
#pragma unroll
    for (int q=0;q<10;q++) acc[q] = 0.f;
#pragma unroll
    for (int i=0;i<8;i++){
        float2 f = c2f(v[i]);
        float I = f.x*f.x + f.y*f.y;
        int cl = d_cls[row*NN + j + 64*brev[i]];
#pragma unroll
        for (int q=0;q<10;q++) if (cl==q) acc[q] += I;
        f = c2f(w[i]);
        I = f.x*f.x + f.y*f.y;
        cl = d_cls[row*NN + j + 32 + 64*brev[i]];
#pragma unroll
        for (int q=0;q<10;q++) if (cl==q) acc[q] += I;
    }
#pragma unroll
    for (int q=0;q<10;q++){
#pragma unroll
        for (int o=16;o>0;o>>=1)
            acc[q] += __shfl_xor_sync(0xffffffffu, acc[q], o);
    }
    if (j == 0){
#pragma unroll
        for (int q=0;q<10;q++) WP[line][q] = acc[q];
    }
    __syncthreads();
    if (t < 10){
        float s = 0.f;
#pragma unroll
        for (int q=0;q<8;q++) s += WP[q][t];
        d_part[(img*64 + chunk)*10 + t] = s;
    }
}

// ---------------- mega kernel: software-pipelined pass dispatch ----------------
__global__ void __launch_bounds__(256,4) mega(int i, int gmin,
                                              const float* __restrict__ xamp,
                                              const float* __restrict__ pn){
    __shared__ __half2 S[8*RSTRIDE];  // half-precision exchange buffer (~18.7KB)
    __shared__ float2 TW[TWSZ];       // skewed fp32 twiddle table
    __shared__ float WP[8][10];
    int t = threadIdx.x;
    TW[SK(t)] = d_tw[t]; TW[SK(t+256)] = d_tw[t+256];
    __syncthreads();                  // TW visible to ALL warps (row bodies use warp syncs only)

    int slice = blockIdx.x / BPS;
    int inner = blockIdx.x - slice * BPS;
    int g = gmin + slice;
    int p = i - g;
    int img0 = g * GSIZE;

    switch (p){
        case 0: body_p1 (S, TW, xamp, pn, inner, img0); break;
        case 1: body_col(S, TW, d_Hb,  inner, img0); break;
        case 2: body_mid(S, TW, 1,     inner, img0); break;
        case 3: body_col(S, TW, d_Hb,  inner, img0); break;
        case 4: body_mid(S, TW, 2,     inner, img0); break;
        case 5: body_col(S, TW, d_Hb2, inner, img0); break;   // fused last two props
        default: body_p7(S, TW, WP,    inner, img0); break;
    }
}

// final: sum over 9 modes x 64 chunks, /9, scores [16,10]
__global__ void redB(float* __restrict__ out){
    __shared__ float sh[64];
    int t = threadIdx.x;
    int b = blockIdx.x / 10, c = blockIdx.x % 10;
    float s = 0.f;
#pragma unroll
    for (int m=0;m<9;m++)
        s += d_part[(((m*16+b) << 6) + t)*10 + c];
    sh[t] = s; __syncthreads();
    for (int w=32; w>0; w>>=1){ if (t < w) sh[t] += sh[t+w]; __syncthreads(); }
    if (t==0) out[blockIdx.x] = sh[0] * (1.0f/9.0f);
}

// ---------------- launch ----------------
extern "C" void kernel_launch(void* const* d_in, const int* in_sizes, int n_in,
                              void* d_out, int out_size){
    const float* x_amp  = (const float*)d_in[0];
    const float* pnoise = (const float*)d_in[1];
    const float* amp    = (const float*)d_in[2];
    const float* phs    = (const float*)d_in[3];
    const float* mask   = (const float*)d_in[4];
    float* out = (float*)d_out;

    k_tw  <<<1,   512>>>();
    k_init<<<512, 512>>>(amp, phs, mask);

    // pipelined schedule: launch i runs pass (i-g) of group g for all valid g
    for (int i = 0; i < NG + 6; i++){
        int gmin = (i > 6) ? (i - 6) : 0;
        int gmax = (i < NG-1) ? i : (NG-1);
        int ns = gmax - gmin + 1;
        mega<<<ns*BPS, 256>>>(i, gmin, x_amp, pnoise);
    }
    redB<<<160, 64>>>(out);
}